// round 5
// baseline (speedup 1.0000x reference)
#include <cuda_runtime.h>
#include <cuda_fp16.h>
#include <math.h>

#define WW    5
#define LL    20
#define ROWI  105      // W*(1+L)
#define CEc   32
#define OCc   30
#define Kc    3
#define WEc   50
#define HIDc  100
#define TAGSc 36
#define QN    256
#define FCIN  400      // (WE+OC)*W
#define WSTR  80       // WE+OC

#define NW 32
#define NT (NW*32)
#define IT 4           // items per warp

#define NQ (WW*QN*HIDc)        // 128000
#define NWP (WW*OCc*HIDc)      // 15000
#define NP (100*OCc)           // 3000

// ---- precomputed tables (device globals: allocation-free scratch) ----
__device__ float  g_P3[100*96];        // [c][k][32-padded oc]  fp32, byte stride 384/char
__device__ float  g_Q [NQ];            // [w][id][j]
__device__ __half g_WpH[NWP];          // [r=w*30+oc][j]  fp16, pre-transposed

typedef unsigned long long u64;
__device__ __forceinline__ float tanh_ap(float x) {
    float y; asm("tanh.approx.f32 %0, %1;" : "=f"(y) : "f"(x)); return y;
}
__device__ __forceinline__ u64 pk2(float lo, float hi){ u64 r; asm("mov.b64 %0, {%1,%2};" : "=l"(r) : "f"(lo), "f"(hi)); return r; }
__device__ __forceinline__ float2 upk2(u64 v){ float2 f; asm("mov.b64 {%0,%1}, %2;" : "=f"(f.x), "=f"(f.y) : "l"(v)); return f; }
__device__ __forceinline__ u64 ffma2(u64 a, u64 b, u64 c){ u64 d; asm("fma.rn.f32x2 %0, %1, %2, %3;" : "=l"(d) : "l"(a), "l"(b), "l"(c)); return d; }
__device__ __forceinline__ u64 fadd2(u64 a, u64 b){ u64 d; asm("add.rn.f32x2 %0, %1, %2;" : "=l"(d) : "l"(a), "l"(b)); return d; }

// one fused prep launch: Q | WpH | P3
__global__ void prep_all(const float* __restrict__ conv_w,
                         const float* __restrict__ char_emb,
                         const float* __restrict__ emb,
                         const float* __restrict__ fc1_w) {
    int i = blockIdx.x*blockDim.x + threadIdx.x;
    if (i < NQ) {
        int j = i % HIDc;
        int c = (i / HIDc) % QN;
        int w = i / (HIDc*QN);
        const float* e  = emb + c*WEc;
        const float* fr = fc1_w + j*FCIN + w*WSTR;
        float s = 0.f;
        #pragma unroll
        for (int d = 0; d < WEc; d++) s += e[d]*fr[d];
        g_Q[i] = s;
    } else if (i < NQ + NWP) {
        int k = i - NQ;
        int j = k % HIDc, r = k / HIDc;
        int w = r / OCc, oc = r % OCc;
        g_WpH[k] = __float2half_rn(fc1_w[j*FCIN + w*WSTR + WEc + oc]);
    } else if (i < NQ + NWP + NP) {
        int k = i - NQ - NWP;
        int oc = k % OCc, c = k / OCc;
        float s0 = 0.f, s1 = 0.f, s2 = 0.f;
        #pragma unroll
        for (int ce = 0; ce < CEc; ce++) {
            float e = char_emb[c*CEc + ce];
            const float* w = &conv_w[(oc*CEc + ce)*Kc];
            s0 += w[0]*e; s1 += w[1]*e; s2 += w[2]*e;
        }
        g_P3[c*96 +  0 + oc] = s0;
        g_P3[c*96 + 32 + oc] = s1;
        g_P3[c*96 + 64 + oc] = s2;
    }
}

// ---- smem layout (bytes) ----
#define OFFB_P3   0          // 38400  float [c][k][32]
#define OFFB_WPH  38400      // 30000  half [r][100]
#define OFFB_OWH  68400      // 36*216 = 7776  half [t][stride 108]
#define OWH_STRIDE 108
#define OFFB_FB   76176      // 400
#define OFFB_OB   76576      // 160
#define OFFB_CB   76736      // 128
#define OFFB_WS   76864      // warp scratch
#define WSB       4848       // ids u16 848 | poolT f32 2400 | sH f32 1600
#define SM_BYTES  (OFFB_WS + NW*WSB)   // 232000

__global__ __launch_bounds__(NT) void pos_main(
    const int*   __restrict__ input,
    const float* __restrict__ emb,
    const float* __restrict__ conv_b,
    const float* __restrict__ fc1_w,
    const float* __restrict__ fc1_b,
    const float* __restrict__ out_w,
    const float* __restrict__ out_b,
    float*       __restrict__ out,
    int nb)
{
    extern __shared__ char smb[];
    __half* sWpH = (__half*)(smb + OFFB_WPH);
    __half* sOwH = (__half*)(smb + OFFB_OWH);
    float*  sFb  = (float*)(smb + OFFB_FB);
    float*  sOb  = (float*)(smb + OFFB_OB);
    float*  sCb  = (float*)(smb + OFFB_CB);

    const int tid = threadIdx.x;

    // -- fill shared weights --
    {
        const int4* ps = (const int4*)g_P3;            // 2400 int4
        int4* pd = (int4*)(smb + OFFB_P3);
        for (int i = tid; i < 2400; i += NT) pd[i] = ps[i];
        const int4* wsrc = (const int4*)g_WpH;         // 1875 int4
        int4* wd = (int4*)sWpH;
        for (int i = tid; i < 1875; i += NT) wd[i] = wsrc[i];
        for (int i = tid; i < TAGSc*OWH_STRIDE; i += NT) {
            int t = i / OWH_STRIDE, j = i % OWH_STRIDE;
            sOwH[i] = (j < HIDc) ? __float2half_rn(out_w[t*HIDc + j]) : __half(0.f);
        }
        if (tid < HIDc)  sFb[tid] = fc1_b[tid];
        if (tid < TAGSc) sOb[tid] = out_b[tid];
        if (tid < OCc)   sCb[tid] = conv_b[tid];
    }
    __syncthreads();

    const int warp = tid >> 5, lane = tid & 31;
    char* ws = smb + OFFB_WS + warp*WSB;
    unsigned short* sIds = (unsigned short*)ws;         // 420 used (u16)
    float* sPoolT = (float*)(ws + 848);                 // [r][IT] 600 f
    float* sH     = (float*)(ws + 3248);                // [it][100] 400 f

    const char* Plane = smb + (lane << 2);              // P3 base + lane*4

    const int j0 = lane*4;
    const bool jact = (lane < 25);
    const int ngroups = (nb + IT - 1) / IT;

    for (int group = blockIdx.x*NW + warp; group < ngroups; group += gridDim.x*NW) {
        const int base = group*IT;
        const int nit = (nb - base < IT) ? (nb - base) : IT;

        // char slots pre-scaled to byte offsets (c*384 < 65536), word slots raw
        for (int i = lane; i < nit*ROWI; i += 32) {
            int v = input[base*ROWI + i];
            sIds[i] = (unsigned short)(((i % 21) == 0) ? v : v*384);
        }
        __syncwarp();

        // -- fc1 accumulators (f32x2 pairs); word-embedding part via Q table --
        u64 a2[IT][2] = {};
        if (jact) {
            for (int it = 0; it < nit; it++) {
                #pragma unroll
                for (int w = 0; w < WW; w++) {
                    int id = sIds[it*ROWI + w*21];
                    if (id < QN) {
                        const ulonglong2 q2 = *(const ulonglong2*)&g_Q[(w*QN + id)*HIDc + j0];
                        a2[it][0] = fadd2(a2[it][0], q2.x);
                        a2[it][1] = fadd2(a2[it][1], q2.y);
                    } else {   // exact fallback (never taken for this data)
                        const float* e = emb + (long)id*WEc;
                        float f0=0.f,f1=0.f,f2=0.f,f3=0.f;
                        #pragma unroll 1
                        for (int d = 0; d < WEc; d++) {
                            float ev = e[d];
                            f0 += ev * fc1_w[(j0+0)*FCIN + w*WSTR + d];
                            f1 += ev * fc1_w[(j0+1)*FCIN + w*WSTR + d];
                            f2 += ev * fc1_w[(j0+2)*FCIN + w*WSTR + d];
                            f3 += ev * fc1_w[(j0+3)*FCIN + w*WSTR + d];
                        }
                        a2[it][0] = fadd2(a2[it][0], pk2(f0,f1));
                        a2[it][1] = fadd2(a2[it][1], pk2(f2,f3));
                    }
                }
            }
        }

        // -- conv + maxpool via fp32 P3; lane == oc; rolling window --
        if (lane < OCc) {
            for (int it = 0; it < nit; it++) {
                #pragma unroll 1
                for (int w = 0; w < WW; w++) {
                    const unsigned short* cc = &sIds[it*ROWI + w*21 + 1];
                    float m = -3.4e38f;
                    float a = 0.f, b = 0.f;
                    #pragma unroll
                    for (int p = 0; p < LL; p++) {
                        const float* row = (const float*)(Plane + cc[p]);
                        float v0 = row[0], v1 = row[32], v2 = row[64];
                        if (p >= 2) m = fmaxf(m, a + v2);
                        a = b + v1;
                        b = v0;
                    }
                    sPoolT[(w*OCc + lane)*IT + it] = m + sCb[lane];
                }
            }
        }
        __syncwarp();

        // -- fc1 pooled part: fp16 weights, f32x2 FMA, then tanh --
        if (jact) {
            const uint2* wp = (const uint2*)sWpH;       // row = 25 uint2
            const float4* pp4 = (const float4*)sPoolT;
            #pragma unroll 2
            for (int r = 0; r < WW*OCc; r++) {
                uint2 wraw = wp[r*25 + lane];
                float2 w01 = __half22float2(*(__half2*)&wraw.x);
                float2 w23 = __half22float2(*(__half2*)&wraw.y);
                u64 pw01 = pk2(w01.x, w01.y);
                u64 pw23 = pk2(w23.x, w23.y);
                float4 pv = pp4[r];
                u64 d0 = pk2(pv.x,pv.x), d1 = pk2(pv.y,pv.y);
                u64 d2 = pk2(pv.z,pv.z), d3 = pk2(pv.w,pv.w);
                a2[0][0] = ffma2(d0,pw01,a2[0][0]); a2[0][1] = ffma2(d0,pw23,a2[0][1]);
                a2[1][0] = ffma2(d1,pw01,a2[1][0]); a2[1][1] = ffma2(d1,pw23,a2[1][1]);
                a2[2][0] = ffma2(d2,pw01,a2[2][0]); a2[2][1] = ffma2(d2,pw23,a2[2][1]);
                a2[3][0] = ffma2(d3,pw01,a2[3][0]); a2[3][1] = ffma2(d3,pw23,a2[3][1]);
            }
            #pragma unroll
            for (int it = 0; it < IT; it++) {
                float2 lo = upk2(a2[it][0]);
                float2 hi = upk2(a2[it][1]);
                float4 hb;
                hb.x = tanh_ap(lo.x + sFb[j0+0]);
                hb.y = tanh_ap(lo.y + sFb[j0+1]);
                hb.z = tanh_ap(hi.x + sFb[j0+2]);
                hb.w = tanh_ap(hi.y + sFb[j0+3]);
                *(float4*)&sH[it*HIDc + j0] = hb;
            }
        }
        __syncwarp();

        // -- output layer main: t = lane (32 tags), j-packed f32x2 FMA --
        u64 o1p[IT] = {0,0,0,0};
        const uint2* owr = (const uint2*)(sOwH + lane*OWH_STRIDE);
        #pragma unroll 5
        for (int jq = 0; jq < HIDc/4; jq++) {
            uint2 raw = owr[jq];
            float2 w01 = __half22float2(*(__half2*)&raw.x);
            float2 w23 = __half22float2(*(__half2*)&raw.y);
            u64 pw01 = pk2(w01.x, w01.y);
            u64 pw23 = pk2(w23.x, w23.y);
            ulonglong2 h0 = *(const ulonglong2*)&sH[0*HIDc + jq*4];
            ulonglong2 h1 = *(const ulonglong2*)&sH[1*HIDc + jq*4];
            ulonglong2 h2 = *(const ulonglong2*)&sH[2*HIDc + jq*4];
            ulonglong2 h3 = *(const ulonglong2*)&sH[3*HIDc + jq*4];
            o1p[0] = ffma2(pw01, h0.x, o1p[0]); o1p[0] = ffma2(pw23, h0.y, o1p[0]);
            o1p[1] = ffma2(pw01, h1.x, o1p[1]); o1p[1] = ffma2(pw23, h1.y, o1p[1]);
            o1p[2] = ffma2(pw01, h2.x, o1p[2]); o1p[2] = ffma2(pw23, h2.y, o1p[2]);
            o1p[3] = ffma2(pw01, h3.x, o1p[3]); o1p[3] = ffma2(pw23, h3.y, o1p[3]);
        }

        // -- output layer tail: tags 32..35, 8 lanes per tag + butterfly --
        float o2a[IT] = {0.f,0.f,0.f,0.f};
        {
            const int tIdx = lane >> 3;            // 0..3 -> tag 32+tIdx
            const int jb   = lane & 7;
            const __half* wrow = sOwH + (32+tIdx)*OWH_STRIDE + jb;
            const float*  hb0  = sH + jb;
            #pragma unroll
            for (int k = 0; k < 13; k++) {
                int j = jb + 8*k;
                if (j < HIDc) {
                    float wv = __half2float(wrow[8*k]);
                    o2a[0] += wv * hb0[0*HIDc + 8*k];
                    o2a[1] += wv * hb0[1*HIDc + 8*k];
                    o2a[2] += wv * hb0[2*HIDc + 8*k];
                    o2a[3] += wv * hb0[3*HIDc + 8*k];
                }
            }
            #pragma unroll
            for (int it = 0; it < IT; it++) {
                o2a[it] += __shfl_xor_sync(0xffffffffu, o2a[it], 1);
                o2a[it] += __shfl_xor_sync(0xffffffffu, o2a[it], 2);
                o2a[it] += __shfl_xor_sync(0xffffffffu, o2a[it], 4);
            }
        }

        for (int it = 0; it < nit; it++) {
            float2 f = upk2(o1p[it]);
            out[(long)(base+it)*TAGSc + lane] = f.x + f.y + sOb[lane];
            if ((lane & 7) == 0)
                out[(long)(base+it)*TAGSc + 32 + (lane>>3)] = o2a[it] + sOb[32 + (lane>>3)];
        }
        __syncwarp();   // protect sIds/sH before next group's overwrite
    }
}

extern "C" void kernel_launch(void* const* d_in, const int* in_sizes, int n_in,
                              void* d_out, int out_size) {
    const int*   input = (const int*)  d_in[0];
    const float* emb   = (const float*)d_in[1];
    const float* cemb  = (const float*)d_in[2];
    const float* convw = (const float*)d_in[3];
    const float* convb = (const float*)d_in[4];
    const float* fc1w  = (const float*)d_in[5];
    const float* fc1b  = (const float*)d_in[6];
    const float* outw  = (const float*)d_in[7];
    const float* outb  = (const float*)d_in[8];
    float* out = (float*)d_out;

    int nb = in_sizes[0] / ROWI;

    cudaFuncSetAttribute(pos_main, cudaFuncAttributeMaxDynamicSharedMemorySize, SM_BYTES);

    int prep_n = NQ + NWP + NP;
    prep_all<<<(prep_n + 255)/256, 256>>>(convw, cemb, emb, fc1w);

    pos_main<<<148, NT, SM_BYTES>>>(input, emb, convb, fc1w, fc1b, outw, outb, out, nb);
}

// round 6
// speedup vs baseline: 1.1953x; 1.1953x over previous
#include <cuda_runtime.h>
#include <cuda_fp16.h>
#include <math.h>

#define WW    5
#define LL    20
#define ROWI  105      // W*(1+L)
#define CEc   32
#define OCc   30
#define Kc    3
#define WEc   50
#define HIDc  100
#define TAGSc 36
#define QN    128
#define FCIN  400      // (WE+OC)*W
#define WSTR  80       // WE+OC

#define NW 32
#define NT (NW*32)
#define IT 4           // items per warp

#define NQ (WW*QN*HIDc)        // 64000
#define NWP (WW*OCc*HIDc)      // 15000
#define NP (100*OCc)           // 3000

// ---- precomputed tables (device globals: allocation-free scratch) ----
__device__ __half g_P4b[100*16*8];     // [c][ocpair(16)][k0lo,k0hi,k1lo,k1hi,k2lo,k2hi,pad,pad]
__device__ float  g_Q [NQ];            // [w][id][j]
__device__ __half g_WpH[NWP];          // [r=w*30+oc][j]  fp16, pre-transposed

__device__ __forceinline__ float tanh_ap(float x) {
    float y; asm("tanh.approx.f32 %0, %1;" : "=f"(y) : "f"(x)); return y;
}

// one fused prep launch: Q | WpH | P4b
__global__ void prep_all(const float* __restrict__ conv_w,
                         const float* __restrict__ char_emb,
                         const float* __restrict__ emb,
                         const float* __restrict__ fc1_w) {
    int i = blockIdx.x*blockDim.x + threadIdx.x;
    if (i < NQ) {
        int j = i % HIDc;
        int c = (i / HIDc) % QN;
        int w = i / (HIDc*QN);
        const float* e  = emb + c*WEc;
        const float* fr = fc1_w + j*FCIN + w*WSTR;
        float s = 0.f;
        #pragma unroll
        for (int d = 0; d < WEc; d++) s += e[d]*fr[d];
        g_Q[i] = s;
    } else if (i < NQ + NWP) {
        int k = i - NQ;
        int j = k % HIDc, r = k / HIDc;
        int w = r / OCc, oc = r % OCc;
        g_WpH[k] = __float2half_rn(fc1_w[j*FCIN + w*WSTR + WEc + oc]);
    } else if (i < NQ + NWP + NP) {
        int k = i - NQ - NWP;
        int oc = k % OCc, c = k / OCc;
        float s0 = 0.f, s1 = 0.f, s2 = 0.f;
        #pragma unroll
        for (int ce = 0; ce < CEc; ce++) {
            float e = char_emb[c*CEc + ce];
            const float* w = &conv_w[(oc*CEc + ce)*Kc];
            s0 += w[0]*e; s1 += w[1]*e; s2 += w[2]*e;
        }
        int pr = oc >> 1, lo = oc & 1;
        __half* dst = &g_P4b[(c*16 + pr)*8];
        dst[0 + lo] = __float2half_rn(s0);
        dst[2 + lo] = __float2half_rn(s1);
        dst[4 + lo] = __float2half_rn(s2);
    }
}

// ---- smem layout (bytes) ----
#define OFFB_P4   0          // 25600  half [c][16][8]  (256B/char row)
#define OFFB_WPH  25600      // 30000  half [r][100]
#define OFFB_OWH  55600      // 36*216 = 7776  half [t][stride 108]
#define OWH_STRIDE 108
#define OFFB_FB   63376      // 400
#define OFFB_OB   63776      // 160
#define OFFB_CB   63936      // 128
#define OFFB_WS   64064      // warp scratch
#define WSB       4848       // ids u16 848 | poolT f32 2400 | sH f32 1600
#define SM_BYTES  (OFFB_WS + NW*WSB)   // 219200

__global__ __launch_bounds__(NT) void pos_main(
    const int*   __restrict__ input,
    const float* __restrict__ emb,
    const float* __restrict__ conv_b,
    const float* __restrict__ fc1_w,
    const float* __restrict__ fc1_b,
    const float* __restrict__ out_w,
    const float* __restrict__ out_b,
    float*       __restrict__ out,
    int nb)
{
    extern __shared__ char smb[];
    __half* sWpH = (__half*)(smb + OFFB_WPH);
    __half* sOwH = (__half*)(smb + OFFB_OWH);
    float*  sFb  = (float*)(smb + OFFB_FB);
    float*  sOb  = (float*)(smb + OFFB_OB);
    float*  sCb  = (float*)(smb + OFFB_CB);

    const int tid = threadIdx.x;

    // -- fill shared weights --
    {
        const int4* ps = (const int4*)g_P4b;           // 1600 int4
        int4* pd = (int4*)(smb + OFFB_P4);
        for (int i = tid; i < 1600; i += NT) pd[i] = ps[i];
        const int4* wsrc = (const int4*)g_WpH;         // 1875 int4
        int4* wd = (int4*)sWpH;
        for (int i = tid; i < 1875; i += NT) wd[i] = wsrc[i];
        for (int i = tid; i < TAGSc*OWH_STRIDE; i += NT) {
            int t = i / OWH_STRIDE, j = i % OWH_STRIDE;
            sOwH[i] = (j < HIDc) ? __float2half_rn(out_w[t*HIDc + j]) : __half(0.f);
        }
        if (tid < HIDc)  sFb[tid] = fc1_b[tid];
        if (tid < TAGSc) sOb[tid] = out_b[tid];
        if (tid < OCc)   sCb[tid] = conv_b[tid];
    }
    __syncthreads();

    const int warp = tid >> 5, lane = tid & 31;
    char* ws = smb + OFFB_WS + warp*WSB;
    unsigned short* sIds = (unsigned short*)ws;         // 420 used (u16)
    float* sPoolT = (float*)(ws + 848);                 // [r][IT] 600 f
    float* sH     = (float*)(ws + 3248);                // [it][100] 400 f

    // conv lane mapping: half-warp = item of pair, lane&15 = oc pair
    const int lp   = lane & 15;             // oc pair 0..14 active
    const int hw   = lane >> 4;             // 0/1 item-of-pair
    const bool cact = (lp < 15);
    const char* Pbase = smb + OFFB_P4 + lp*16;
    float cb0 = 0.f, cb1 = 0.f;
    if (cact) { cb0 = sCb[2*lp]; cb1 = sCb[2*lp+1]; }

    const int j0 = lane*4;
    const bool jact = (lane < 25);
    const int ngroups = (nb + IT - 1) / IT;

    for (int group = blockIdx.x*NW + warp; group < ngroups; group += gridDim.x*NW) {
        const int base = group*IT;
        const int nit = (nb - base < IT) ? (nb - base) : IT;

        // char slots pre-scaled to row byte offsets (c*256 <= 25344), word slots raw
        for (int i = lane; i < nit*ROWI; i += 32) {
            int v = input[base*ROWI + i];
            sIds[i] = (unsigned short)(((i % 21) == 0) ? v : (v << 8));
        }
        if (nit < IT) {  // tail safety: zero missing items' slots
            for (int i = nit*ROWI + lane; i < IT*ROWI; i += 32) sIds[i] = 0;
        }
        __syncwarp();

        // -- fc1 accumulators; word-embedding part via Q table --
        float a[IT][4] = {};
        if (jact) {
            for (int it = 0; it < nit; it++) {
                #pragma unroll
                for (int w = 0; w < WW; w++) {
                    int id = sIds[it*ROWI + w*21];
                    if (id < QN) {
                        const float4 q = *(const float4*)&g_Q[(w*QN + id)*HIDc + j0];
                        a[it][0] += q.x; a[it][1] += q.y; a[it][2] += q.z; a[it][3] += q.w;
                    } else {   // exact fallback (never taken for this data)
                        const float* e = emb + (long)id*WEc;
                        #pragma unroll 1
                        for (int d = 0; d < WEc; d++) {
                            float ev = e[d];
                            a[it][0] += ev * fc1_w[(j0+0)*FCIN + w*WSTR + d];
                            a[it][1] += ev * fc1_w[(j0+1)*FCIN + w*WSTR + d];
                            a[it][2] += ev * fc1_w[(j0+2)*FCIN + w*WSTR + d];
                            a[it][3] += ev * fc1_w[(j0+3)*FCIN + w*WSTR + d];
                        }
                    }
                }
            }
        }

        // -- conv + maxpool: 2 items/warp-pass, half2 over oc pairs --
        if (cact) {
            #pragma unroll
            for (int ip = 0; ip < 2; ip++) {
                const int it = ip*2 + hw;
                #pragma unroll 1
                for (int w = 0; w < WW; w++) {
                    const unsigned short* cc = &sIds[it*ROWI + w*21 + 1];
                    __half2 m  = __floats2half2_rn(-60000.f, -60000.f);
                    __half2 s1 = __floats2half2_rn(0.f, 0.f);
                    __half2 s0 = s1;
                    #pragma unroll
                    for (int p = 0; p < LL; p++) {
                        const uint4 raw = *(const uint4*)(Pbase + cc[p]);
                        __half2 v0 = *(const __half2*)&raw.x;
                        __half2 v1 = *(const __half2*)&raw.y;
                        __half2 v2 = *(const __half2*)&raw.z;
                        if (p >= 2) m = __hmax2(m, __hadd2(s1, v2));
                        s1 = __hadd2(s0, v1);
                        s0 = v0;
                    }
                    float2 fm = __half22float2(m);
                    sPoolT[(w*OCc + 2*lp  )*IT + it] = fm.x + cb0;
                    sPoolT[(w*OCc + 2*lp+1)*IT + it] = fm.y + cb1;
                }
            }
        }
        __syncwarp();

        // -- fc1 pooled part: fp16 weights reused across IT items, then tanh --
        if (jact) {
            const uint2* wp = (const uint2*)sWpH;       // row = 25 uint2
            const float4* pp4 = (const float4*)sPoolT;
            #pragma unroll 2
            for (int r = 0; r < WW*OCc; r++) {
                uint2 wraw = wp[r*25 + lane];
                float2 w01 = __half22float2(*(__half2*)&wraw.x);
                float2 w23 = __half22float2(*(__half2*)&wraw.y);
                float4 pv = pp4[r];                     // [item0..3] broadcast
                a[0][0] += pv.x*w01.x; a[0][1] += pv.x*w01.y; a[0][2] += pv.x*w23.x; a[0][3] += pv.x*w23.y;
                a[1][0] += pv.y*w01.x; a[1][1] += pv.y*w01.y; a[1][2] += pv.y*w23.x; a[1][3] += pv.y*w23.y;
                a[2][0] += pv.z*w01.x; a[2][1] += pv.z*w01.y; a[2][2] += pv.z*w23.x; a[2][3] += pv.z*w23.y;
                a[3][0] += pv.w*w01.x; a[3][1] += pv.w*w01.y; a[3][2] += pv.w*w23.x; a[3][3] += pv.w*w23.y;
            }
            #pragma unroll
            for (int it = 0; it < IT; it++) {
                float4 hb;
                hb.x = tanh_ap(a[it][0] + sFb[j0+0]);
                hb.y = tanh_ap(a[it][1] + sFb[j0+1]);
                hb.z = tanh_ap(a[it][2] + sFb[j0+2]);
                hb.w = tanh_ap(a[it][3] + sFb[j0+3]);
                *(float4*)&sH[it*HIDc + j0] = hb;
            }
        }
        __syncwarp();

        // -- output layer main: t = lane (32 tags), fp32 math, fp16 weights --
        float o1[IT] = {0.f,0.f,0.f,0.f};
        const uint2* owr = (const uint2*)(sOwH + lane*OWH_STRIDE);
        #pragma unroll 5
        for (int jq = 0; jq < HIDc/4; jq++) {
            uint2 raw = owr[jq];
            float2 w01 = __half22float2(*(__half2*)&raw.x);
            float2 w23 = __half22float2(*(__half2*)&raw.y);
            float4 h0 = *(const float4*)&sH[0*HIDc + jq*4];
            float4 h1 = *(const float4*)&sH[1*HIDc + jq*4];
            float4 h2 = *(const float4*)&sH[2*HIDc + jq*4];
            float4 h3 = *(const float4*)&sH[3*HIDc + jq*4];
            o1[0] += w01.x*h0.x + w01.y*h0.y + w23.x*h0.z + w23.y*h0.w;
            o1[1] += w01.x*h1.x + w01.y*h1.y + w23.x*h1.z + w23.y*h1.w;
            o1[2] += w01.x*h2.x + w01.y*h2.y + w23.x*h2.z + w23.y*h2.w;
            o1[3] += w01.x*h3.x + w01.y*h3.y + w23.x*h3.z + w23.y*h3.w;
        }

        // -- output layer tail: tags 32..35, 8 lanes per tag + butterfly --
        float o2a[IT] = {0.f,0.f,0.f,0.f};
        {
            const int tIdx = lane >> 3;            // tag 32+tIdx
            const int jb   = lane & 7;
            const __half* wrow = sOwH + (32+tIdx)*OWH_STRIDE + jb;
            const float*  hb0  = sH + jb;
            #pragma unroll
            for (int k = 0; k < 12; k++) {
                float wv = __half2float(wrow[8*k]);
                o2a[0] += wv * hb0[0*HIDc + 8*k];
                o2a[1] += wv * hb0[1*HIDc + 8*k];
                o2a[2] += wv * hb0[2*HIDc + 8*k];
                o2a[3] += wv * hb0[3*HIDc + 8*k];
            }
            if (jb < 4) {                          // j = 96..99
                float wv = __half2float(wrow[96]);
                o2a[0] += wv * hb0[0*HIDc + 96];
                o2a[1] += wv * hb0[1*HIDc + 96];
                o2a[2] += wv * hb0[2*HIDc + 96];
                o2a[3] += wv * hb0[3*HIDc + 96];
            }
            #pragma unroll
            for (int it = 0; it < IT; it++) {
                o2a[it] += __shfl_xor_sync(0xffffffffu, o2a[it], 1);
                o2a[it] += __shfl_xor_sync(0xffffffffu, o2a[it], 2);
                o2a[it] += __shfl_xor_sync(0xffffffffu, o2a[it], 4);
            }
        }

        for (int it = 0; it < nit; it++) {
            out[(long)(base+it)*TAGSc + lane] = o1[it] + sOb[lane];
            if ((lane & 7) == 0)
                out[(long)(base+it)*TAGSc + 32 + (lane>>3)] = o2a[it] + sOb[32 + (lane>>3)];
        }
        __syncwarp();   // protect sIds/sH before next group's overwrite
    }
}

extern "C" void kernel_launch(void* const* d_in, const int* in_sizes, int n_in,
                              void* d_out, int out_size) {
    const int*   input = (const int*)  d_in[0];
    const float* emb   = (const float*)d_in[1];
    const float* cemb  = (const float*)d_in[2];
    const float* convw = (const float*)d_in[3];
    const float* convb = (const float*)d_in[4];
    const float* fc1w  = (const float*)d_in[5];
    const float* fc1b  = (const float*)d_in[6];
    const float* outw  = (const float*)d_in[7];
    const float* outb  = (const float*)d_in[8];
    float* out = (float*)d_out;

    int nb = in_sizes[0] / ROWI;

    cudaFuncSetAttribute(pos_main, cudaFuncAttributeMaxDynamicSharedMemorySize, SM_BYTES);

    int prep_n = NQ + NWP + NP;
    prep_all<<<(prep_n + 255)/256, 256>>>(convw, cemb, emb, fc1w);

    pos_main<<<148, NT, SM_BYTES>>>(input, emb, convb, fc1w, fc1b, outw, outb, out, nb);
}

// round 7
// speedup vs baseline: 1.4229x; 1.1905x over previous
#include <cuda_runtime.h>
#include <cuda_fp16.h>
#include <math.h>
#include <stdint.h>

#define WW    5
#define LL    20
#define ROWI  105      // W*(1+L)
#define CEc   32
#define OCc   30
#define Kc    3
#define WEc   50
#define HIDc  100
#define TAGSc 36
#define QN    128
#define FCIN  400      // (WE+OC)*W
#define WSTR  80       // WE+OC

#define NW 32
#define NT (NW*32)
#define IT 4           // items per warp

#define KTILES 10      // K padded 150 -> 160
#define NTILES 13      // N padded 100 -> 104
#define NFRAG  (KTILES*NTILES)   // 130

#define NQ  (WW*QN*HIDc)         // 64000
#define NB_ (NFRAG*32)           // 4160 lane-entries, 4 halves each
#define NP  (100*OCc)            // 3000

// ---- precomputed tables (device globals: allocation-free scratch) ----
__device__ __half g_P4b[100*16*8];   // [c][ocpair(16)][k0lo,k0hi,k1lo,k1hi,k2lo,k2hi,pad,pad]
__device__ float  g_Q [NQ];          // [w][id][j]
__device__ __half g_WpB[NB_*4];      // B fragments: [(kt*13+nt)*32+lane][4 halves]

__device__ __forceinline__ float tanh_ap(float x) {
    float y; asm("tanh.approx.f32 %0, %1;" : "=f"(y) : "f"(x)); return y;
}
__device__ __forceinline__ void mma16816(float& c0, float& c1, float& c2, float& c3,
        uint32_t a0, uint32_t a1, uint32_t a2, uint32_t a3, uint32_t b0, uint32_t b1) {
    asm volatile("mma.sync.aligned.m16n8k16.row.col.f32.f16.f16.f32 "
        "{%0,%1,%2,%3}, {%4,%5,%6,%7}, {%8,%9}, {%0,%1,%2,%3};"
        : "+f"(c0), "+f"(c1), "+f"(c2), "+f"(c3)
        : "r"(a0), "r"(a1), "r"(a2), "r"(a3), "r"(b0), "r"(b1));
}

// one fused prep launch: Q | WpB frags | P4b
__global__ void prep_all(const float* __restrict__ conv_w,
                         const float* __restrict__ char_emb,
                         const float* __restrict__ emb,
                         const float* __restrict__ fc1_w) {
    int i = blockIdx.x*blockDim.x + threadIdx.x;
    if (i < NQ) {
        int j = i % HIDc;
        int c = (i / HIDc) % QN;
        int w = i / (HIDc*QN);
        const float* e  = emb + c*WEc;
        const float* fr = fc1_w + j*FCIN + w*WSTR;
        float s = 0.f;
        #pragma unroll
        for (int d = 0; d < WEc; d++) s += e[d]*fr[d];
        g_Q[i] = s;
    } else if (i < NQ + NB_) {
        int e = i - NQ;
        int lane = e & 31, tile = e >> 5;
        int kt = tile / NTILES, nt = tile % NTILES;
        int n = nt*8 + (lane >> 2);
        int kb = kt*16 + (lane & 3)*2;
        const int koff[4] = {0, 1, 8, 9};
        __half* dst = &g_WpB[e*4];
        #pragma unroll
        for (int q = 0; q < 4; q++) {
            int k = kb + koff[q];
            float v = 0.f;
            if (k < WW*OCc && n < HIDc) {
                int w = k / OCc, oc = k % OCc;
                v = fc1_w[n*FCIN + w*WSTR + WEc + oc];
            }
            dst[q] = __float2half_rn(v);
        }
    } else if (i < NQ + NB_ + NP) {
        int k = i - NQ - NB_;
        int oc = k % OCc, c = k / OCc;
        float s0 = 0.f, s1 = 0.f, s2 = 0.f;
        #pragma unroll
        for (int ce = 0; ce < CEc; ce++) {
            float e = char_emb[c*CEc + ce];
            const float* w = &conv_w[(oc*CEc + ce)*Kc];
            s0 += w[0]*e; s1 += w[1]*e; s2 += w[2]*e;
        }
        int pr = oc >> 1, lo = oc & 1;
        __half* dst = &g_P4b[(c*16 + pr)*8];
        dst[0 + lo] = __float2half_rn(s0);
        dst[2 + lo] = __float2half_rn(s1);
        dst[4 + lo] = __float2half_rn(s2);
    }
}

// ---- smem layout (bytes) ----
#define OFFB_P4   0          // 25600  half [c][16][8]  (256B/char row)
#define OFFB_WB   25600      // 33280  half B-frag table
#define OFFB_OWH  58880      // 36*216 = 7776  half [t][stride 108]
#define OWH_STRIDE 108
#define OFFB_FB   66656      // 400
#define OFFB_OB   67056      // 160
#define OFFB_CB   67216      // 128
#define OFFB_WS   67344      // warp scratch (16B aligned)
#define WSB       3792       // ids u16 848 | pool fp16 [4][160] 1280 | Qs/sH f32 [4][104] 1664
#define SM_BYTES  (OFFB_WS + NW*WSB)   // 188688

template<int NT0, int NTN>
__device__ __forceinline__ void mma_pass(const __half* pool16, const char* sWB,
                                         float* Qs, int lane) {
    const int lr = lane >> 2;       // A row / C row (items 0-3 on rows 0-3)
    const int lq = lane & 3;
    float C[NTN][4];
    #pragma unroll
    for (int t = 0; t < NTN; t++) { C[t][0]=0.f; C[t][1]=0.f; C[t][2]=0.f; C[t][3]=0.f; }
    #pragma unroll
    for (int kt = 0; kt < KTILES; kt++) {
        uint32_t a0 = *(const uint32_t*)&pool16[lr*160 + kt*16 + lq*2];
        uint32_t a2 = *(const uint32_t*)&pool16[lr*160 + kt*16 + lq*2 + 8];
        #pragma unroll
        for (int t = 0; t < NTN; t++) {
            uint2 b = *(const uint2*)(sWB + ((kt*NTILES + NT0 + t)*32 + lane)*8);
            mma16816(C[t][0], C[t][1], C[t][2], C[t][3], a0, a0, a2, a2, b.x, b.y);
        }
    }
    // epilogue: items on rows 0-3 (lanes 0-15), cols (NT0+t)*8 + lq*2, +1
    if (lane < 16) {
        #pragma unroll
        for (int t = 0; t < NTN; t++) {
            int col = (NT0 + t)*8 + lq*2;
            float2 qv = *(float2*)&Qs[lr*104 + col];
            float2 hv;
            hv.x = tanh_ap(C[t][0] + qv.x);
            hv.y = tanh_ap(C[t][1] + qv.y);
            *(float2*)&Qs[lr*104 + col] = hv;
        }
    }
}

__global__ __launch_bounds__(NT) void pos_main(
    const int*   __restrict__ input,
    const float* __restrict__ emb,
    const float* __restrict__ conv_b,
    const float* __restrict__ fc1_w,
    const float* __restrict__ fc1_b,
    const float* __restrict__ out_w,
    const float* __restrict__ out_b,
    float*       __restrict__ out,
    int nb)
{
    extern __shared__ char smb[];
    const char* sWB = smb + OFFB_WB;
    __half* sOwH = (__half*)(smb + OFFB_OWH);
    float*  sFb  = (float*)(smb + OFFB_FB);
    float*  sOb  = (float*)(smb + OFFB_OB);
    float*  sCb  = (float*)(smb + OFFB_CB);

    const int tid = threadIdx.x;

    // -- fill shared tables --
    {
        const int4* ps = (const int4*)g_P4b;           // 1600 int4
        int4* pd = (int4*)(smb + OFFB_P4);
        for (int i = tid; i < 1600; i += NT) pd[i] = ps[i];
        const int4* bs = (const int4*)g_WpB;           // 2080 int4
        int4* bd = (int4*)(smb + OFFB_WB);
        for (int i = tid; i < 2080; i += NT) bd[i] = bs[i];
        for (int i = tid; i < TAGSc*OWH_STRIDE; i += NT) {
            int t = i / OWH_STRIDE, j = i % OWH_STRIDE;
            sOwH[i] = (j < HIDc) ? __float2half_rn(out_w[t*HIDc + j]) : __half(0.f);
        }
        if (tid < HIDc)  sFb[tid] = fc1_b[tid];
        if (tid < TAGSc) sOb[tid] = out_b[tid];
        if (tid < OCc)   sCb[tid] = conv_b[tid];
    }
    __syncthreads();

    const int warp = tid >> 5, lane = tid & 31;
    char* ws = smb + OFFB_WS + warp*WSB;
    unsigned short* sIds = (unsigned short*)ws;         // 420 u16 used
    __half* pool16 = (__half*)(ws + 848);               // [it][160] fp16
    float*  Qs     = (float*)(ws + 2128);               // [it][104] f32; becomes sH in-place

    // conv lane mapping: half-warp = item of pair, lane&15 = oc pair
    const int lp   = lane & 15;
    const int hw   = lane >> 4;
    const bool cact = (lp < 15);
    const char* Pbase = smb + OFFB_P4 + lp*16;
    __half2 cbh = __floats2half2_rn(0.f, 0.f);
    if (cact) cbh = __floats2half2_rn(sCb[2*lp], sCb[2*lp+1]);

    const int j0 = lane*4;
    const int ngroups = (nb + IT - 1) / IT;

    for (int group = blockIdx.x*NW + warp; group < ngroups; group += gridDim.x*NW) {
        const int base = group*IT;
        const int nit = (nb - base < IT) ? (nb - base) : IT;

        // char slots pre-scaled to row byte offsets (c*256), word slots raw
        for (int i = lane; i < nit*ROWI; i += 32) {
            int v = input[base*ROWI + i];
            sIds[i] = (unsigned short)(((i % 21) == 0) ? v : (v << 8));
        }
        if (nit < IT)
            for (int i = nit*ROWI + lane; i < IT*ROWI; i += 32) sIds[i] = 0;
        // zero K-pad region of pool (k=150..159 per item)
        for (int i = lane; i < 40; i += 32)
            pool16[(i/10)*160 + 150 + (i%10)] = __half(0.f);
        __syncwarp();

        // -- conv + maxpool: 2 items/pass, half2 over oc pairs -> pool fp16 row-major --
        if (cact) {
            #pragma unroll
            for (int ip = 0; ip < 2; ip++) {
                const int it = ip*2 + hw;
                #pragma unroll 1
                for (int w = 0; w < WW; w++) {
                    const unsigned short* cc = &sIds[it*ROWI + w*21 + 1];
                    __half2 m  = __floats2half2_rn(-60000.f, -60000.f);
                    __half2 s1 = __floats2half2_rn(0.f, 0.f);
                    __half2 s0 = s1;
                    #pragma unroll
                    for (int p = 0; p < LL; p++) {
                        const uint4 raw = *(const uint4*)(Pbase + cc[p]);
                        __half2 v0 = *(const __half2*)&raw.x;
                        __half2 v1 = *(const __half2*)&raw.y;
                        __half2 v2 = *(const __half2*)&raw.z;
                        if (p >= 2) m = __hmax2(m, __hadd2(s1, v2));
                        s1 = __hadd2(s0, v1);
                        s0 = v0;
                    }
                    *(__half2*)&pool16[it*160 + w*OCc + 2*lp] = __hadd2(m, cbh);
                }
            }
        }
        __syncwarp();

        // -- Q phase: Qs[it][j] = sum_w Qtable + fc1_b (fp32), j in [0,104) --
        if (lane < 26) {
            for (int it = 0; it < IT; it++) {
                float4 acc = {0.f, 0.f, 0.f, 0.f};
                if (lane < 25) {
                    if (it < nit) {
                        #pragma unroll
                        for (int w = 0; w < WW; w++) {
                            int id = sIds[it*ROWI + w*21];
                            if (id < QN) {
                                const float4 q = *(const float4*)&g_Q[(w*QN + id)*HIDc + j0];
                                acc.x += q.x; acc.y += q.y; acc.z += q.z; acc.w += q.w;
                            } else {   // exact fallback (never taken for this data)
                                const float* e = emb + (long)id*WEc;
                                #pragma unroll 1
                                for (int d = 0; d < WEc; d++) {
                                    float ev = e[d];
                                    acc.x += ev * fc1_w[(j0+0)*FCIN + w*WSTR + d];
                                    acc.y += ev * fc1_w[(j0+1)*FCIN + w*WSTR + d];
                                    acc.z += ev * fc1_w[(j0+2)*FCIN + w*WSTR + d];
                                    acc.w += ev * fc1_w[(j0+3)*FCIN + w*WSTR + d];
                                }
                            }
                        }
                    }
                    acc.x += sFb[j0+0]; acc.y += sFb[j0+1];
                    acc.z += sFb[j0+2]; acc.w += sFb[j0+3];
                }
                *(float4*)&Qs[it*104 + j0] = acc;
            }
        }
        __syncwarp();

        // -- fc1 pooled part on tensor cores + tanh epilogue (in-place: Qs -> sH) --
        mma_pass<0, 7>(pool16, sWB, Qs, lane);
        mma_pass<7, 6>(pool16, sWB, Qs, lane);
        __syncwarp();

        // -- output layer main: t = lane (32 tags), fp32 math, fp16 weights --
        const float* sH = Qs;   // stride 104
        float o1[IT] = {0.f,0.f,0.f,0.f};
        const uint2* owr = (const uint2*)(sOwH + lane*OWH_STRIDE);
        #pragma unroll 5
        for (int jq = 0; jq < HIDc/4; jq++) {
            uint2 raw = owr[jq];
            float2 w01 = __half22float2(*(__half2*)&raw.x);
            float2 w23 = __half22float2(*(__half2*)&raw.y);
            float4 h0 = *(const float4*)&sH[0*104 + jq*4];
            float4 h1 = *(const float4*)&sH[1*104 + jq*4];
            float4 h2 = *(const float4*)&sH[2*104 + jq*4];
            float4 h3 = *(const float4*)&sH[3*104 + jq*4];
            o1[0] += w01.x*h0.x + w01.y*h0.y + w23.x*h0.z + w23.y*h0.w;
            o1[1] += w01.x*h1.x + w01.y*h1.y + w23.x*h1.z + w23.y*h1.w;
            o1[2] += w01.x*h2.x + w01.y*h2.y + w23.x*h2.z + w23.y*h2.w;
            o1[3] += w01.x*h3.x + w01.y*h3.y + w23.x*h3.z + w23.y*h3.w;
        }

        // -- output layer tail: tags 32..35, 8 lanes per tag + butterfly --
        float o2a[IT] = {0.f,0.f,0.f,0.f};
        {
            const int tIdx = lane >> 3;
            const int jb   = lane & 7;
            const __half* wrow = sOwH + (32+tIdx)*OWH_STRIDE + jb;
            const float*  hb0  = sH + jb;
            #pragma unroll
            for (int k = 0; k < 12; k++) {
                float wv = __half2float(wrow[8*k]);
                o2a[0] += wv * hb0[0*104 + 8*k];
                o2a[1] += wv * hb0[1*104 + 8*k];
                o2a[2] += wv * hb0[2*104 + 8*k];
                o2a[3] += wv * hb0[3*104 + 8*k];
            }
            if (jb < 4) {                          // j = 96..99
                float wv = __half2float(wrow[96]);
                o2a[0] += wv * hb0[0*104 + 96];
                o2a[1] += wv * hb0[1*104 + 96];
                o2a[2] += wv * hb0[2*104 + 96];
                o2a[3] += wv * hb0[3*104 + 96];
            }
            #pragma unroll
            for (int it = 0; it < IT; it++) {
                o2a[it] += __shfl_xor_sync(0xffffffffu, o2a[it], 1);
                o2a[it] += __shfl_xor_sync(0xffffffffu, o2a[it], 2);
                o2a[it] += __shfl_xor_sync(0xffffffffu, o2a[it], 4);
            }
        }

        for (int it = 0; it < nit; it++) {
            out[(long)(base+it)*TAGSc + lane] = o1[it] + sOb[lane];
            if ((lane & 7) == 0)
                out[(long)(base+it)*TAGSc + 32 + (lane>>3)] = o2a[it] + sOb[32 + (lane>>3)];
        }
        __syncwarp();   // protect scratch before next group's overwrite
    }
}

extern "C" void kernel_launch(void* const* d_in, const int* in_sizes, int n_in,
                              void* d_out, int out_size) {
    const int*   input = (const int*)  d_in[0];
    const float* emb   = (const float*)d_in[1];
    const float* cemb  = (const float*)d_in[2];
    const float* convw = (const float*)d_in[3];
    const float* convb = (const float*)d_in[4];
    const float* fc1w  = (const float*)d_in[5];
    const float* fc1b  = (const float*)d_in[6];
    const float* outw  = (const float*)d_in[7];
    const float* outb  = (const float*)d_in[8];
    float* out = (float*)d_out;

    int nb = in_sizes[0] / ROWI;

    cudaFuncSetAttribute(pos_main, cudaFuncAttributeMaxDynamicSharedMemorySize, SM_BYTES);

    int prep_n = NQ + NB_ + NP;
    prep_all<<<(prep_n + 255)/256, 256>>>(convw, cemb, emb, fc1w);

    pos_main<<<148, NT, SM_BYTES>>>(input, emb, convb, fc1w, fc1b, outw, outb, out, nb);
}

// round 8
// speedup vs baseline: 1.5913x; 1.1183x over previous
#include <cuda_runtime.h>
#include <cuda_fp16.h>
#include <math.h>
#include <stdint.h>

#define WW    5
#define LL    20
#define ROWI  105      // W*(1+L)
#define CEc   32
#define OCc   30
#define Kc    3
#define WEc   50
#define HIDc  100
#define TAGSc 36
#define QN    128
#define FCIN  400      // (WE+OC)*W
#define WSTR  80       // WE+OC

#define NW 32
#define NT (NW*32)
#define IT 4           // items per warp

#define KTILES 10      // fc1 K padded 150 -> 160
#define NTILES 13      // fc1 N padded 100 -> 104
#define NFRAG  (KTILES*NTILES)   // 130

#define KT2 7          // out K padded 104 -> 112
#define NT2 5          // out N padded 36 -> 40
#define NFRAG2 (KT2*NT2)         // 35

#define NQ   (WW*QN*HIDc)        // 64000
#define NB_  (NFRAG*32)          // 4160
#define NB2_ (NFRAG2*32)         // 1120
#define NP   (100*OCc)           // 3000

// ---- precomputed tables (device globals: allocation-free scratch) ----
__device__ __half g_P4b[100*16*8];   // [c][ocpair(16)][k0lo,k0hi,k1lo,k1hi,k2lo,k2hi,pad,pad]
__device__ float  g_Q [NQ];          // [w][id][j]
__device__ __half g_WpB[NB_*4];      // fc1 B frags: [(kt*13+nt)*32+lane][4 halves]
__device__ __half g_OwB[NB2_*4];     // out B frags: [(kt*5+nt)*32+lane][4 halves]

__device__ __forceinline__ float tanh_ap(float x) {
    float y; asm("tanh.approx.f32 %0, %1;" : "=f"(y) : "f"(x)); return y;
}
__device__ __forceinline__ void mma16816(float& c0, float& c1, float& c2, float& c3,
        uint32_t a0, uint32_t a1, uint32_t a2, uint32_t a3, uint32_t b0, uint32_t b1) {
    asm volatile("mma.sync.aligned.m16n8k16.row.col.f32.f16.f16.f32 "
        "{%0,%1,%2,%3}, {%4,%5,%6,%7}, {%8,%9}, {%0,%1,%2,%3};"
        : "+f"(c0), "+f"(c1), "+f"(c2), "+f"(c3)
        : "r"(a0), "r"(a1), "r"(a2), "r"(a3), "r"(b0), "r"(b1));
}

// one fused prep launch: Q | WpB | OwB | P4b
__global__ void prep_all(const float* __restrict__ conv_w,
                         const float* __restrict__ char_emb,
                         const float* __restrict__ emb,
                         const float* __restrict__ fc1_w,
                         const float* __restrict__ out_w) {
    int i = blockIdx.x*blockDim.x + threadIdx.x;
    if (i < NQ) {
        int j = i % HIDc;
        int c = (i / HIDc) % QN;
        int w = i / (HIDc*QN);
        const float* e  = emb + c*WEc;
        const float* fr = fc1_w + j*FCIN + w*WSTR;
        float s = 0.f;
        #pragma unroll
        for (int d = 0; d < WEc; d++) s += e[d]*fr[d];
        g_Q[i] = s;
    } else if (i < NQ + NB_) {
        int e = i - NQ;
        int lane = e & 31, tile = e >> 5;
        int kt = tile / NTILES, nt = tile % NTILES;
        int n = nt*8 + (lane >> 2);
        int kb = kt*16 + (lane & 3)*2;
        const int koff[4] = {0, 1, 8, 9};
        __half* dst = &g_WpB[e*4];
        #pragma unroll
        for (int q = 0; q < 4; q++) {
            int k = kb + koff[q];
            float v = 0.f;
            if (k < WW*OCc && n < HIDc) {
                int w = k / OCc, oc = k % OCc;
                v = fc1_w[n*FCIN + w*WSTR + WEc + oc];
            }
            dst[q] = __float2half_rn(v);
        }
    } else if (i < NQ + NB_ + NB2_) {
        int e = i - NQ - NB_;
        int lane = e & 31, tile = e >> 5;
        int kt = tile / NT2, nt = tile % NT2;
        int n = nt*8 + (lane >> 2);       // tag
        int kb = kt*16 + (lane & 3)*2;    // hidden j
        const int koff[4] = {0, 1, 8, 9};
        __half* dst = &g_OwB[e*4];
        #pragma unroll
        for (int q = 0; q < 4; q++) {
            int k = kb + koff[q];
            float v = (k < HIDc && n < TAGSc) ? out_w[n*HIDc + k] : 0.f;
            dst[q] = __float2half_rn(v);
        }
    } else if (i < NQ + NB_ + NB2_ + NP) {
        int k = i - NQ - NB_ - NB2_;
        int oc = k % OCc, c = k / OCc;
        float s0 = 0.f, s1 = 0.f, s2 = 0.f;
        #pragma unroll
        for (int ce = 0; ce < CEc; ce++) {
            float e = char_emb[c*CEc + ce];
            const float* w = &conv_w[(oc*CEc + ce)*Kc];
            s0 += w[0]*e; s1 += w[1]*e; s2 += w[2]*e;
        }
        int pr = oc >> 1, lo = oc & 1;
        __half* dst = &g_P4b[(c*16 + pr)*8];
        dst[0 + lo] = __float2half_rn(s0);
        dst[2 + lo] = __float2half_rn(s1);
        dst[4 + lo] = __float2half_rn(s2);
    }
}

// ---- smem layout (bytes) ----
#define OFFB_P4   0          // 25600  half [c][16][8]  (256B/char row)
#define OFFB_WB   25600      // 33280  fc1 B-frag table
#define OFFB_WB2  58880      // 8960   out B-frag table
#define OFFB_FB   67840      // 400    fc1_b
#define OFFB_OB   68240      // 160    out_b (40 slots)
#define OFFB_CB   68400      // 128    conv_b
#define OFFB_WS   68528      // warp scratch (16B aligned)
#define WSB       4704       // ids u16 864 | pool16 [4][160] 1280 | Qs f32 [4][104] 1664 | sH16 [4][112] 896
#define SM_BYTES  (OFFB_WS + NW*WSB + 1024)   // +1KB tail pad for benign OOB frag reads

template<int NT0, int NTN>
__device__ __forceinline__ void mma_fc1(const __half* pool16, const char* sWB,
                                        const float* Qs, __half* sH16, int lane) {
    const int lr = lane >> 2;       // A/C row (items 0-3 on rows 0-3)
    const int lq = lane & 3;
    float C[NTN][4];
    #pragma unroll
    for (int t = 0; t < NTN; t++) { C[t][0]=0.f; C[t][1]=0.f; C[t][2]=0.f; C[t][3]=0.f; }
    #pragma unroll
    for (int kt = 0; kt < KTILES; kt++) {
        uint32_t a0 = *(const uint32_t*)&pool16[lr*160 + kt*16 + lq*2];
        uint32_t a2 = *(const uint32_t*)&pool16[lr*160 + kt*16 + lq*2 + 8];
        #pragma unroll
        for (int t = 0; t < NTN; t++) {
            uint2 b = *(const uint2*)(sWB + ((kt*NTILES + NT0 + t)*32 + lane)*8);
            mma16816(C[t][0], C[t][1], C[t][2], C[t][3], a0, a0, a2, a2, b.x, b.y);
        }
    }
    if (lane < 16) {
        #pragma unroll
        for (int t = 0; t < NTN; t++) {
            int col = (NT0 + t)*8 + lq*2;
            float2 qv = *(const float2*)&Qs[lr*104 + col];
            __half2 hv = __floats2half2_rn(tanh_ap(C[t][0] + qv.x),
                                           tanh_ap(C[t][1] + qv.y));
            *(__half2*)&sH16[lr*112 + col] = hv;
        }
    }
}

__global__ __launch_bounds__(NT) void pos_main(
    const int*   __restrict__ input,
    const float* __restrict__ emb,
    const float* __restrict__ conv_b,
    const float* __restrict__ fc1_w,
    const float* __restrict__ fc1_b,
    const float* __restrict__ out_b,
    float*       __restrict__ out,
    int nb)
{
    extern __shared__ char smb[];
    const char* sWB  = smb + OFFB_WB;
    const char* sWB2 = smb + OFFB_WB2;
    float*  sFb  = (float*)(smb + OFFB_FB);
    float*  sOb  = (float*)(smb + OFFB_OB);
    float*  sCb  = (float*)(smb + OFFB_CB);

    const int tid = threadIdx.x;

    // -- fill shared tables --
    {
        const int4* ps = (const int4*)g_P4b;           // 1600 int4
        int4* pd = (int4*)(smb + OFFB_P4);
        for (int i = tid; i < 1600; i += NT) pd[i] = ps[i];
        const int4* bs = (const int4*)g_WpB;           // 2080 int4
        int4* bd = (int4*)(smb + OFFB_WB);
        for (int i = tid; i < 2080; i += NT) bd[i] = bs[i];
        const int4* b2 = (const int4*)g_OwB;           // 560 int4
        int4* bd2 = (int4*)(smb + OFFB_WB2);
        for (int i = tid; i < 560; i += NT) bd2[i] = b2[i];
        if (tid < HIDc)  sFb[tid] = fc1_b[tid];
        if (tid < TAGSc) sOb[tid] = out_b[tid];
        if (tid < OCc)   sCb[tid] = conv_b[tid];
    }
    __syncthreads();

    const int warp = tid >> 5, lane = tid & 31;
    char* ws = smb + OFFB_WS + warp*WSB;
    unsigned short* sIds = (unsigned short*)ws;         // 420 u16 used
    __half* pool16 = (__half*)(ws + 864);               // [it][160] fp16
    float*  Qs     = (float*)(ws + 2144);               // [it][104] f32
    __half* sH16   = (__half*)(ws + 3808);              // [it][112] fp16

    // one-time pad zeroing (pool cols 150-159, sH16 cols 104-111, rows 0-3)
    for (int i = lane; i < 40; i += 32)
        pool16[(i/10)*160 + 150 + (i%10)] = __half(0.f);
    if (lane < 16)
        *(uint32_t*)&sH16[(lane >> 2)*112 + 104 + (lane & 3)*2] = 0u;

    // conv lane mapping: half-warp = item of pair, lane&15 = oc pair
    const int lp   = lane & 15;
    const int hw   = lane >> 4;
    const bool cact = (lp < 15);
    const char* Pbase = smb + OFFB_P4 + lp*16;
    __half2 cbh = __floats2half2_rn(0.f, 0.f);
    if (cact) cbh = __floats2half2_rn(sCb[2*lp], sCb[2*lp+1]);

    const int j0 = lane*4;
    const int lr = lane >> 2, lq = lane & 3;
    const int ngroups = (nb + IT - 1) / IT;

    for (int group = blockIdx.x*NW + warp; group < ngroups; group += gridDim.x*NW) {
        const int base = group*IT;
        const int nit = (nb - base < IT) ? (nb - base) : IT;

        // char slots pre-scaled to row byte offsets (c*256), word slots raw
        for (int i = lane; i < nit*ROWI; i += 32) {
            int v = input[base*ROWI + i];
            sIds[i] = (unsigned short)(((i % 21) == 0) ? v : (v << 8));
        }
        if (nit < IT)
            for (int i = nit*ROWI + lane; i < IT*ROWI; i += 32) sIds[i] = 0;
        __syncwarp();

        // -- conv + maxpool: 2 items/pass, half2 over oc pairs -> pool fp16 --
        if (cact) {
            #pragma unroll
            for (int ip = 0; ip < 2; ip++) {
                const int it = ip*2 + hw;
                #pragma unroll 1
                for (int w = 0; w < WW; w++) {
                    const unsigned short* cc = &sIds[it*ROWI + w*21 + 1];
                    __half2 m  = __floats2half2_rn(-60000.f, -60000.f);
                    __half2 s1 = __floats2half2_rn(0.f, 0.f);
                    __half2 s0 = s1;
                    #pragma unroll
                    for (int p = 0; p < LL; p++) {
                        const uint4 raw = *(const uint4*)(Pbase + cc[p]);
                        __half2 v0 = *(const __half2*)&raw.x;
                        __half2 v1 = *(const __half2*)&raw.y;
                        __half2 v2 = *(const __half2*)&raw.z;
                        if (p >= 2) m = __hmax2(m, __hadd2(s1, v2));
                        s1 = __hadd2(s0, v1);
                        s0 = v0;
                    }
                    *(__half2*)&pool16[it*160 + w*OCc + 2*lp] = __hadd2(m, cbh);
                }
            }
        }
        __syncwarp();

        // -- Q phase: Qs[it][j] = sum_w Qtable + fc1_b (fp32) --
        if (lane < 26) {
            for (int it = 0; it < IT; it++) {
                float4 acc = {0.f, 0.f, 0.f, 0.f};
                if (lane < 25) {
                    if (it < nit) {
                        #pragma unroll
                        for (int w = 0; w < WW; w++) {
                            int id = sIds[it*ROWI + w*21];
                            if (id < QN) {
                                const float4 q = *(const float4*)&g_Q[(w*QN + id)*HIDc + j0];
                                acc.x += q.x; acc.y += q.y; acc.z += q.z; acc.w += q.w;
                            } else {   // exact fallback (never taken for this data)
                                const float* e = emb + (long)id*WEc;
                                #pragma unroll 1
                                for (int d = 0; d < WEc; d++) {
                                    float ev = e[d];
                                    acc.x += ev * fc1_w[(j0+0)*FCIN + w*WSTR + d];
                                    acc.y += ev * fc1_w[(j0+1)*FCIN + w*WSTR + d];
                                    acc.z += ev * fc1_w[(j0+2)*FCIN + w*WSTR + d];
                                    acc.w += ev * fc1_w[(j0+3)*FCIN + w*WSTR + d];
                                }
                            }
                        }
                    }
                    acc.x += sFb[j0+0]; acc.y += sFb[j0+1];
                    acc.z += sFb[j0+2]; acc.w += sFb[j0+3];
                }
                *(float4*)&Qs[it*104 + j0] = acc;
            }
        }
        __syncwarp();

        // -- fc1 on tensor cores + tanh epilogue -> sH16 fp16 --
        mma_fc1<0, 7>(pool16, sWB, Qs, sH16, lane);
        mma_fc1<7, 6>(pool16, sWB, Qs, sH16, lane);
        __syncwarp();

        // -- output layer on tensor cores: out[4x40] = sH16[4x112] @ OwB --
        {
            float C[NT2][4];
            #pragma unroll
            for (int t = 0; t < NT2; t++) { C[t][0]=0.f; C[t][1]=0.f; C[t][2]=0.f; C[t][3]=0.f; }
            #pragma unroll
            for (int kt = 0; kt < KT2; kt++) {
                uint32_t a0 = *(const uint32_t*)&sH16[lr*112 + kt*16 + lq*2];
                uint32_t a2 = *(const uint32_t*)&sH16[lr*112 + kt*16 + lq*2 + 8];
                #pragma unroll
                for (int t = 0; t < NT2; t++) {
                    uint2 b = *(const uint2*)(sWB2 + ((kt*NT2 + t)*32 + lane)*8);
                    mma16816(C[t][0], C[t][1], C[t][2], C[t][3], a0, a0, a2, a2, b.x, b.y);
                }
            }
            if (lane < 16 && lr < nit) {
                float* orow = out + (long)(base + lr)*TAGSc;
                #pragma unroll
                for (int t = 0; t < NT2; t++) {
                    int c = t*8 + lq*2;
                    if (c < TAGSc)     orow[c]     = C[t][0] + sOb[c];
                    if (c + 1 < TAGSc) orow[c + 1] = C[t][1] + sOb[c + 1];
                }
            }
        }
        __syncwarp();   // protect scratch before next group's overwrite
    }
}

extern "C" void kernel_launch(void* const* d_in, const int* in_sizes, int n_in,
                              void* d_out, int out_size) {
    const int*   input = (const int*)  d_in[0];
    const float* emb   = (const float*)d_in[1];
    const float* cemb  = (const float*)d_in[2];
    const float* convw = (const float*)d_in[3];
    const float* convb = (const float*)d_in[4];
    const float* fc1w  = (const float*)d_in[5];
    const float* fc1b  = (const float*)d_in[6];
    const float* outw  = (const float*)d_in[7];
    const float* outb  = (const float*)d_in[8];
    float* out = (float*)d_out;

    int nb = in_sizes[0] / ROWI;

    cudaFuncSetAttribute(pos_main, cudaFuncAttributeMaxDynamicSharedMemorySize, SM_BYTES);

    int prep_n = NQ + NB_ + NB2_ + NP;
    prep_all<<<(prep_n + 255)/256, 256>>>(convw, cemb, emb, fc1w, outw);

    pos_main<<<148, NT, SM_BYTES>>>(input, emb, convb, fc1w, fc1b, outb, out, nb);
}

// round 9
// speedup vs baseline: 1.8555x; 1.1660x over previous
#include <cuda_runtime.h>
#include <cuda_fp16.h>
#include <math.h>
#include <stdint.h>

#define WW    5
#define LL    20
#define ROWI  105      // W*(1+L)
#define CEc   32
#define OCc   30
#define Kc    3
#define WEc   50
#define HIDc  100
#define TAGSc 36
#define QN    128
#define FCIN  400      // (WE+OC)*W
#define WSTR  80       // WE+OC

#define NW 32
#define NT (NW*32)
#define IT 4           // items per warp

#define KTILES 10      // fc1 K padded 150 -> 160
#define NTILES 13      // fc1 N padded 100 -> 104
#define NFRAG  (KTILES*NTILES)   // 130

#define KT2 7          // out K padded 104 -> 112
#define NT2 5          // out N padded 36 -> 40
#define NFRAG2 (KT2*NT2)         // 35

#define NQ   (WW*QN*HIDc)        // 64000
#define NB_  (NFRAG*32)          // 4160
#define NB2_ (NFRAG2*32)         // 1120
#define NP   (100*OCc)           // 3000
#define QCB  40                  // Q-coop blocks: 5 w x 8 chunks of 16 ids

// ---- precomputed tables (device globals: allocation-free scratch) ----
// P layout per char (256B): [0,120): 15 x (k0lo,k0hi,k1lo,k1hi) 8B pairs
//                           [128,188): k2 pairs copy for hw=0
//                           [192,252): k2 pairs copy for hw=1
__device__ __half g_P4b[100*128];
__device__ float  g_Q [NQ];          // [w][id][j]
__device__ __half g_WpB[NB_*4];      // fc1 B frags: [(kt*13+nt)*32+lane][4 halves]
__device__ __half g_OwB[NB2_*4];     // out B frags: [(kt*5+nt)*32+lane][4 halves]

__device__ __forceinline__ float tanh_ap(float x) {
    float y; asm("tanh.approx.f32 %0, %1;" : "=f"(y) : "f"(x)); return y;
}
__device__ __forceinline__ void mma16816(float& c0, float& c1, float& c2, float& c3,
        uint32_t a0, uint32_t a1, uint32_t a2, uint32_t a3, uint32_t b0, uint32_t b1) {
    asm volatile("mma.sync.aligned.m16n8k16.row.col.f32.f16.f16.f32 "
        "{%0,%1,%2,%3}, {%4,%5,%6,%7}, {%8,%9}, {%0,%1,%2,%3};"
        : "+f"(c0), "+f"(c1), "+f"(c2), "+f"(c3)
        : "r"(a0), "r"(a1), "r"(a2), "r"(a3), "r"(b0), "r"(b1));
}

// one prep launch: blocks [0,QCB) compute Q cooperatively (coalesced);
// remaining blocks do thread-per-output WpB | OwB | P4b
__global__ void prep_all(const float* __restrict__ conv_w,
                         const float* __restrict__ char_emb,
                         const float* __restrict__ emb,
                         const float* __restrict__ fc1_w,
                         const float* __restrict__ out_w) {
    __shared__ float sF[HIDc*WEc];   // 20000B: fc1 word-part [j][d]
    __shared__ float sE[16*WEc];     // 3200B : emb rows for 16 ids
    const int tid = threadIdx.x;

    if (blockIdx.x < QCB) {
        int w = blockIdx.x >> 3, chunk = blockIdx.x & 7;
        for (int i = tid; i < HIDc*WEc; i += 256) {
            int j = i / WEc, d = i % WEc;
            sF[i] = fc1_w[j*FCIN + w*WSTR + d];
        }
        int c0 = chunk*16;
        for (int i = tid; i < 16*WEc; i += 256)
            sE[i] = emb[(c0 + i/WEc)*WEc + (i % WEc)];
        __syncthreads();
        for (int o = tid; o < 16*HIDc; o += 256) {
            int cl = o / HIDc, j = o % HIDc;
            const float* e = &sE[cl*WEc];
            const float* f = &sF[j*WEc];
            float s = 0.f;
            #pragma unroll
            for (int d = 0; d < WEc; d++) s += e[d]*f[d];
            g_Q[(w*QN + c0 + cl)*HIDc + j] = s;
        }
        return;
    }

    int i = (blockIdx.x - QCB)*256 + tid;
    if (i < NB_) {
        int lane = i & 31, tile = i >> 5;
        int kt = tile / NTILES, nt = tile % NTILES;
        int n = nt*8 + (lane >> 2);
        int kb = kt*16 + (lane & 3)*2;
        const int koff[4] = {0, 1, 8, 9};
        __half* dst = &g_WpB[i*4];
        #pragma unroll
        for (int q = 0; q < 4; q++) {
            int k = kb + koff[q];
            float v = 0.f;
            if (k < WW*OCc && n < HIDc) {
                int w = k / OCc, oc = k % OCc;
                v = fc1_w[n*FCIN + w*WSTR + WEc + oc];
            }
            dst[q] = __float2half_rn(v);
        }
    } else if (i < NB_ + NB2_) {
        int e = i - NB_;
        int lane = e & 31, tile = e >> 5;
        int kt = tile / NT2, nt = tile % NT2;
        int n = nt*8 + (lane >> 2);       // tag
        int kb = kt*16 + (lane & 3)*2;    // hidden j
        const int koff[4] = {0, 1, 8, 9};
        __half* dst = &g_OwB[e*4];
        #pragma unroll
        for (int q = 0; q < 4; q++) {
            int k = kb + koff[q];
            float v = (k < HIDc && n < TAGSc) ? out_w[n*HIDc + k] : 0.f;
            dst[q] = __float2half_rn(v);
        }
    } else if (i < NB_ + NB2_ + NP) {
        int k = i - NB_ - NB2_;
        int oc = k % OCc, c = k / OCc;
        float s0 = 0.f, s1 = 0.f, s2 = 0.f;
        #pragma unroll
        for (int ce = 0; ce < CEc; ce++) {
            float e = char_emb[c*CEc + ce];
            const float* w = &conv_w[(oc*CEc + ce)*Kc];
            s0 += w[0]*e; s1 += w[1]*e; s2 += w[2]*e;
        }
        int pr = oc >> 1, lo = oc & 1;
        __half* row = &g_P4b[c*128];
        row[pr*4 + lo]      = __float2half_rn(s0);   // k0
        row[pr*4 + 2 + lo]  = __float2half_rn(s1);   // k1
        __half h2v = __float2half_rn(s2);
        row[64 + pr*2 + lo] = h2v;                   // k2 copy (hw=0)
        row[96 + pr*2 + lo] = h2v;                   // k2 copy (hw=1)
    }
}

// ---- smem layout (bytes) ----
#define OFFB_P4   0          // 25600  half [c][128]  (256B/char row)
#define OFFB_WB   25600      // 33280  fc1 B-frag table
#define OFFB_WB2  58880      // 8960   out B-frag table
#define OFFB_FB   67840      // 400    fc1_b
#define OFFB_OB   68240      // 160    out_b (40 slots)
#define OFFB_CB   68400      // 128    conv_b
#define OFFB_WS   68528      // warp scratch (16B aligned)
#define WSB       4704       // ids u16 864 | pool16 [4][160] 1280 | Qs f32 [4][104] 1664 | sH16 [4][112] 896
#define SM_BYTES  (OFFB_WS + NW*WSB + 1024)   // +1KB tail pad for benign OOB frag reads

template<int NT0, int NTN>
__device__ __forceinline__ void mma_fc1(const __half* pool16, const char* sWB,
                                        const float* Qs, __half* sH16, int lane) {
    const int lr = lane >> 2;       // A/C row (items 0-3 on rows 0-3)
    const int lq = lane & 3;
    float C[NTN][4];
    #pragma unroll
    for (int t = 0; t < NTN; t++) { C[t][0]=0.f; C[t][1]=0.f; C[t][2]=0.f; C[t][3]=0.f; }
    #pragma unroll
    for (int kt = 0; kt < KTILES; kt++) {
        uint32_t a0 = *(const uint32_t*)&pool16[lr*160 + kt*16 + lq*2];
        uint32_t a2 = *(const uint32_t*)&pool16[lr*160 + kt*16 + lq*2 + 8];
        #pragma unroll
        for (int t = 0; t < NTN; t++) {
            uint2 b = *(const uint2*)(sWB + ((kt*NTILES + NT0 + t)*32 + lane)*8);
            mma16816(C[t][0], C[t][1], C[t][2], C[t][3], a0, a0, a2, a2, b.x, b.y);
        }
    }
    if (lane < 16) {
        #pragma unroll
        for (int t = 0; t < NTN; t++) {
            int col = (NT0 + t)*8 + lq*2;
            float2 qv = *(const float2*)&Qs[lr*104 + col];
            __half2 hv = __floats2half2_rn(tanh_ap(C[t][0] + qv.x),
                                           tanh_ap(C[t][1] + qv.y));
            *(__half2*)&sH16[lr*112 + col] = hv;
        }
    }
}

__global__ __launch_bounds__(NT) void pos_main(
    const int*   __restrict__ input,
    const float* __restrict__ emb,
    const float* __restrict__ conv_b,
    const float* __restrict__ fc1_w,
    const float* __restrict__ fc1_b,
    const float* __restrict__ out_b,
    float*       __restrict__ out,
    int nb)
{
    extern __shared__ char smb[];
    const char* sWB  = smb + OFFB_WB;
    const char* sWB2 = smb + OFFB_WB2;
    float*  sFb  = (float*)(smb + OFFB_FB);
    float*  sOb  = (float*)(smb + OFFB_OB);
    float*  sCb  = (float*)(smb + OFFB_CB);

    const int tid = threadIdx.x;

    // -- fill shared tables --
    {
        const int4* ps = (const int4*)g_P4b;           // 1600 int4
        int4* pd = (int4*)(smb + OFFB_P4);
        for (int i = tid; i < 1600; i += NT) pd[i] = ps[i];
        const int4* bs = (const int4*)g_WpB;           // 2080 int4
        int4* bd = (int4*)(smb + OFFB_WB);
        for (int i = tid; i < 2080; i += NT) bd[i] = bs[i];
        const int4* b2 = (const int4*)g_OwB;           // 560 int4
        int4* bd2 = (int4*)(smb + OFFB_WB2);
        for (int i = tid; i < 560; i += NT) bd2[i] = b2[i];
        if (tid < HIDc)  sFb[tid] = fc1_b[tid];
        if (tid < TAGSc) sOb[tid] = out_b[tid];
        if (tid < OCc)   sCb[tid] = conv_b[tid];
    }
    __syncthreads();

    const int warp = tid >> 5, lane = tid & 31;
    char* ws = smb + OFFB_WS + warp*WSB;
    unsigned short* sIds = (unsigned short*)ws;         // 420 u16 used
    __half* pool16 = (__half*)(ws + 864);               // [it][160] fp16
    float*  Qs     = (float*)(ws + 2144);               // [it][104] f32
    __half* sH16   = (__half*)(ws + 3808);              // [it][112] fp16

    // one-time pad zeroing (pool cols 150-159, sH16 cols 104-111, rows 0-3)
    for (int i = lane; i < 40; i += 32)
        pool16[(i/10)*160 + 150 + (i%10)] = __half(0.f);
    if (lane < 16)
        *(uint32_t*)&sH16[(lane >> 2)*112 + 104 + (lane & 3)*2] = 0u;

    // conv lane mapping: half-warp = item of pair, lane&15 = oc pair
    const int lp   = lane & 15;
    const int hw   = lane >> 4;
    const bool cact = (lp < 15);
    const char* Pk01 = smb + OFFB_P4 + lp*8;             // (k0,k1) pairs
    const char* Pk2  = smb + OFFB_P4 + 128 + hw*64 + lp*4; // k2, per-halfwarp copy
    __half2 cbh = __floats2half2_rn(0.f, 0.f);
    if (cact) cbh = __floats2half2_rn(sCb[2*lp], sCb[2*lp+1]);

    const int j0 = lane*4;
    const int lr = lane >> 2, lq = lane & 3;
    const int ngroups = (nb + IT - 1) / IT;

    for (int group = blockIdx.x*NW + warp; group < ngroups; group += gridDim.x*NW) {
        const int base = group*IT;
        const int nit = (nb - base < IT) ? (nb - base) : IT;

        // char slots pre-scaled to row byte offsets (c*256), word slots raw
        for (int i = lane; i < nit*ROWI; i += 32) {
            int v = input[base*ROWI + i];
            sIds[i] = (unsigned short)(((i % 21) == 0) ? v : (v << 8));
        }
        if (nit < IT)
            for (int i = nit*ROWI + lane; i < IT*ROWI; i += 32) sIds[i] = 0;
        __syncwarp();

        // -- conv + maxpool: 2 items/pass, half2 over oc pairs -> pool fp16 --
        if (cact) {
            #pragma unroll
            for (int ip = 0; ip < 2; ip++) {
                const int it = ip*2 + hw;
                #pragma unroll 1
                for (int w = 0; w < WW; w++) {
                    const unsigned short* cc = &sIds[it*ROWI + w*21 + 1];
                    __half2 m  = __floats2half2_rn(-60000.f, -60000.f);
                    __half2 s1 = __floats2half2_rn(0.f, 0.f);
                    __half2 s0 = s1;
                    #pragma unroll
                    for (int p = 0; p < LL; p++) {
                        const int c = cc[p];
                        uint2    r01 = *(const uint2*)(Pk01 + c);
                        uint32_t r2v = *(const uint32_t*)(Pk2 + c);
                        __half2 v0 = *(const __half2*)&r01.x;
                        __half2 v1 = *(const __half2*)&r01.y;
                        __half2 v2 = *(const __half2*)&r2v;
                        if (p >= 2) m = __hmax2(m, __hadd2(s1, v2));
                        s1 = __hadd2(s0, v1);
                        s0 = v0;
                    }
                    *(__half2*)&pool16[it*160 + w*OCc + 2*lp] = __hadd2(m, cbh);
                }
            }
        }
        __syncwarp();

        // -- Q phase: Qs[it][j] = sum_w Qtable + fc1_b (fp32) --
        if (lane < 26) {
            for (int it = 0; it < IT; it++) {
                float4 acc = {0.f, 0.f, 0.f, 0.f};
                if (lane < 25) {
                    if (it < nit) {
                        #pragma unroll
                        for (int w = 0; w < WW; w++) {
                            int id = sIds[it*ROWI + w*21];
                            if (id < QN) {
                                const float4 q = *(const float4*)&g_Q[(w*QN + id)*HIDc + j0];
                                acc.x += q.x; acc.y += q.y; acc.z += q.z; acc.w += q.w;
                            } else {   // exact fallback (never taken for this data)
                                const float* e = emb + (long)id*WEc;
                                #pragma unroll 1
                                for (int d = 0; d < WEc; d++) {
                                    float ev = e[d];
                                    acc.x += ev * fc1_w[(j0+0)*FCIN + w*WSTR + d];
                                    acc.y += ev * fc1_w[(j0+1)*FCIN + w*WSTR + d];
                                    acc.z += ev * fc1_w[(j0+2)*FCIN + w*WSTR + d];
                                    acc.w += ev * fc1_w[(j0+3)*FCIN + w*WSTR + d];
                                }
                            }
                        }
                    }
                    acc.x += sFb[j0+0]; acc.y += sFb[j0+1];
                    acc.z += sFb[j0+2]; acc.w += sFb[j0+3];
                }
                *(float4*)&Qs[it*104 + j0] = acc;
            }
        }
        __syncwarp();

        // -- fc1 on tensor cores + tanh epilogue -> sH16 fp16 --
        mma_fc1<0, 7>(pool16, sWB, Qs, sH16, lane);
        mma_fc1<7, 6>(pool16, sWB, Qs, sH16, lane);
        __syncwarp();

        // -- output layer on tensor cores: out[4x40] = sH16[4x112] @ OwB --
        {
            float C[NT2][4];
            #pragma unroll
            for (int t = 0; t < NT2; t++) { C[t][0]=0.f; C[t][1]=0.f; C[t][2]=0.f; C[t][3]=0.f; }
            #pragma unroll
            for (int kt = 0; kt < KT2; kt++) {
                uint32_t a0 = *(const uint32_t*)&sH16[lr*112 + kt*16 + lq*2];
                uint32_t a2 = *(const uint32_t*)&sH16[lr*112 + kt*16 + lq*2 + 8];
                #pragma unroll
                for (int t = 0; t < NT2; t++) {
                    uint2 b = *(const uint2*)(sWB2 + ((kt*NT2 + t)*32 + lane)*8);
                    mma16816(C[t][0], C[t][1], C[t][2], C[t][3], a0, a0, a2, a2, b.x, b.y);
                }
            }
            if (lane < 16 && lr < nit) {
                float* orow = out + (long)(base + lr)*TAGSc;
                #pragma unroll
                for (int t = 0; t < NT2; t++) {
                    int c = t*8 + lq*2;
                    if (c < TAGSc)     orow[c]     = C[t][0] + sOb[c];
                    if (c + 1 < TAGSc) orow[c + 1] = C[t][1] + sOb[c + 1];
                }
            }
        }
        __syncwarp();   // protect scratch before next group's overwrite
    }
}

extern "C" void kernel_launch(void* const* d_in, const int* in_sizes, int n_in,
                              void* d_out, int out_size) {
    const int*   input = (const int*)  d_in[0];
    const float* emb   = (const float*)d_in[1];
    const float* cemb  = (const float*)d_in[2];
    const float* convw = (const float*)d_in[3];
    const float* convb = (const float*)d_in[4];
    const float* fc1w  = (const float*)d_in[5];
    const float* fc1b  = (const float*)d_in[6];
    const float* outw  = (const float*)d_in[7];
    const float* outb  = (const float*)d_in[8];
    float* out = (float*)d_out;

    int nb = in_sizes[0] / ROWI;

    cudaFuncSetAttribute(pos_main, cudaFuncAttributeMaxDynamicSharedMemorySize, SM_BYTES);

    int tail_blocks = (NB_ + NB2_ + NP + 255)/256;     // 33
    prep_all<<<QCB + tail_blocks, 256>>>(convw, cemb, emb, fc1w, outw);

    pos_main<<<148, NT, SM_BYTES>>>(input, emb, convb, fc1w, fc1b, outb, out, nb);
}

// round 12
// speedup vs baseline: 2.0858x; 1.1241x over previous
#include <cuda_runtime.h>
#include <cuda_fp16.h>
#include <math.h>
#include <stdint.h>

#define WW    5
#define LL    20
#define ROWI  105      // W*(1+L)
#define CEc   32
#define OCc   30
#define Kc    3
#define WEc   50
#define HIDc  100
#define TAGSc 36
#define QN    128
#define FCIN  400      // (WE+OC)*W
#define WSTR  80       // WE+OC

#define NW 32
#define NT (NW*32)
#define NPAIR 16
#define ITP 8          // items per warp-pair

#define KTILES 10      // fc1 K padded 150 -> 160
#define NTILES 13      // fc1 N padded 100 -> 104
#define NFRAG  (KTILES*NTILES)   // 130

#define KT2 7          // out K padded 104 -> 112
#define NT2 5          // out N padded 36 -> 40
#define NFRAG2 (KT2*NT2)         // 35

#define NQ   (WW*QN*HIDc)        // 64000
#define NB_  (NFRAG*32)          // 4160
#define NB2_ (NFRAG2*32)         // 1120
#define NP   (100*OCc)           // 3000
#define QCB  80                  // Q-coop blocks: 5 w x 16 chunks of 8 ids

// ---- precomputed tables (device globals: allocation-free scratch) ----
// P layout per char (256B): [0,120): 15 x (k0lo,k0hi,k1lo,k1hi) 8B pairs
//                           [128,188): k2 pairs copy for hw=0
//                           [192,252): k2 pairs copy for hw=1
__device__ __half g_P4b[100*128];
__device__ float  g_Q [NQ];          // [w][id][j]
__device__ __half g_WpB[NB_*4];      // fc1 B frags: [(kt*13+nt)*32+lane][4 halves]
__device__ __half g_OwB[NB2_*4];     // out B frags: [(kt*5+nt)*32+lane][4 halves]

__device__ __forceinline__ float tanh_ap(float x) {
    float y; asm("tanh.approx.f32 %0, %1;" : "=f"(y) : "f"(x)); return y;
}
__device__ __forceinline__ void mma16816(float& c0, float& c1, float& c2, float& c3,
        uint32_t a0, uint32_t a1, uint32_t a2, uint32_t a3, uint32_t b0, uint32_t b1) {
    asm volatile("mma.sync.aligned.m16n8k16.row.col.f32.f16.f16.f32 "
        "{%0,%1,%2,%3}, {%4,%5,%6,%7}, {%8,%9}, {%0,%1,%2,%3};"
        : "+f"(c0), "+f"(c1), "+f"(c2), "+f"(c3)
        : "r"(a0), "r"(a1), "r"(a2), "r"(a3), "r"(b0), "r"(b1));
}
__device__ __forceinline__ void pair_bar(int id) {
    asm volatile("bar.sync %0, %1;" :: "r"(id), "r"(64) : "memory");
}

// one prep launch: blocks [0,QCB) compute Q cooperatively (coalesced);
// remaining blocks do thread-per-output WpB | OwB | P4b
__global__ void prep_all(const float* __restrict__ conv_w,
                         const float* __restrict__ char_emb,
                         const float* __restrict__ emb,
                         const float* __restrict__ fc1_w,
                         const float* __restrict__ out_w) {
    __shared__ float sF[HIDc*WEc];   // 20000B: fc1 word-part [j][d]
    __shared__ float sE[8*WEc];      // emb rows for 8 ids
    const int tid = threadIdx.x;

    if (blockIdx.x < QCB) {
        int w = blockIdx.x >> 4, chunk = blockIdx.x & 15;
        for (int i = tid; i < HIDc*WEc; i += 256) {
            int j = i / WEc, d = i % WEc;
            sF[i] = fc1_w[j*FCIN + w*WSTR + d];
        }
        int c0 = chunk*8;
        for (int i = tid; i < 8*WEc; i += 256)
            sE[i] = emb[(c0 + i/WEc)*WEc + (i % WEc)];
        __syncthreads();
        for (int o = tid; o < 8*HIDc; o += 256) {
            int cl = o / HIDc, j = o % HIDc;
            const float* e = &sE[cl*WEc];
            const float* f = &sF[j*WEc];
            float s = 0.f;
            #pragma unroll
            for (int d = 0; d < WEc; d++) s += e[d]*f[d];
            g_Q[(w*QN + c0 + cl)*HIDc + j] = s;
        }
        return;
    }

    int i = (blockIdx.x - QCB)*256 + tid;
    if (i < NB_) {
        int lane = i & 31, tile = i >> 5;
        int kt = tile / NTILES, nt = tile % NTILES;
        int n = nt*8 + (lane >> 2);
        int kb = kt*16 + (lane & 3)*2;
        const int koff[4] = {0, 1, 8, 9};
        __half* dst = &g_WpB[i*4];
        #pragma unroll
        for (int q = 0; q < 4; q++) {
            int k = kb + koff[q];
            float v = 0.f;
            if (k < WW*OCc && n < HIDc) {
                int w = k / OCc, oc = k % OCc;
                v = fc1_w[n*FCIN + w*WSTR + WEc + oc];
            }
            dst[q] = __float2half_rn(v);
        }
    } else if (i < NB_ + NB2_) {
        int e = i - NB_;
        int lane = e & 31, tile = e >> 5;
        int kt = tile / NT2, nt = tile % NT2;
        int n = nt*8 + (lane >> 2);       // tag
        int kb = kt*16 + (lane & 3)*2;    // hidden j
        const int koff[4] = {0, 1, 8, 9};
        __half* dst = &g_OwB[e*4];
        #pragma unroll
        for (int q = 0; q < 4; q++) {
            int k = kb + koff[q];
            float v = (k < HIDc && n < TAGSc) ? out_w[n*HIDc + k] : 0.f;
            dst[q] = __float2half_rn(v);
        }
    } else if (i < NB_ + NB2_ + NP) {
        int k = i - NB_ - NB2_;
        int oc = k % OCc, c = k / OCc;
        float s0 = 0.f, s1 = 0.f, s2 = 0.f;
        #pragma unroll
        for (int ce = 0; ce < CEc; ce++) {
            float e = char_emb[c*CEc + ce];
            const float* w = &conv_w[(oc*CEc + ce)*Kc];
            s0 += w[0]*e; s1 += w[1]*e; s2 += w[2]*e;
        }
        int pr = oc >> 1, lo = oc & 1;
        __half* row = &g_P4b[c*128];
        row[pr*4 + lo]      = __float2half_rn(s0);   // k0
        row[pr*4 + 2 + lo]  = __float2half_rn(s1);   // k1
        __half h2v = __float2half_rn(s2);
        row[64 + pr*2 + lo] = h2v;                   // k2 copy (hw=0)
        row[96 + pr*2 + lo] = h2v;                   // k2 copy (hw=1)
    }
}

// ---- smem layout (bytes) ----
#define OFFB_P4   0          // 25600  half [c][128]  (256B/char row)
#define OFFB_WB   25600      // 33280  fc1 B-frag table
#define OFFB_WB2  58880      // 8960   out B-frag table
#define OFFB_FB   67840      // 400    fc1_b
#define OFFB_OB   68240      // 160    out_b (40 slots)
#define OFFB_CB   68400      // 128    conv_b
#define OFFB_WS   68528      // pair scratch (16B aligned)
// per-pair scratch: ids u16 [8*105] 1680->1696 | pool16 [8][160] 2560 | Qs f32 [8][104] 3328 | sH16 [8][112] 1792
#define PSB       9376
#define POOL_OFF  1696
#define QS_OFF    4256
#define SH_OFF    7584
#define SM_BYTES  (OFFB_WS + NPAIR*PSB + 1024)   // 219568 (+pad for benign OOB frag reads)

// fc1 mma over 8 A-rows (items 0-7), N-tiles [NT0, NT0+NTN)
template<int NT0, int NTN>
__device__ __forceinline__ void mma_fc1(const __half* pool16, const char* sWB,
                                        const float* Qs, __half* sH16, int lane) {
    const int lr = lane >> 2;       // A/C row = item 0..7
    const int lq = lane & 3;
    float C[NTN][4];
    #pragma unroll
    for (int t = 0; t < NTN; t++) { C[t][0]=0.f; C[t][1]=0.f; C[t][2]=0.f; C[t][3]=0.f; }
    #pragma unroll
    for (int kt = 0; kt < KTILES; kt++) {
        uint32_t a0 = *(const uint32_t*)&pool16[lr*160 + kt*16 + lq*2];
        uint32_t a2 = *(const uint32_t*)&pool16[lr*160 + kt*16 + lq*2 + 8];
        #pragma unroll
        for (int t = 0; t < NTN; t++) {
            uint2 b = *(const uint2*)(sWB + ((kt*NTILES + NT0 + t)*32 + lane)*8);
            mma16816(C[t][0], C[t][1], C[t][2], C[t][3], a0, a0, a2, a2, b.x, b.y);
        }
    }
    // epilogue: all 32 lanes, rows 0-7, cols (NT0+t)*8 + lq*2
    #pragma unroll
    for (int t = 0; t < NTN; t++) {
        int col = (NT0 + t)*8 + lq*2;
        float2 qv = *(const float2*)&Qs[lr*104 + col];
        __half2 hv = __floats2half2_rn(tanh_ap(C[t][0] + qv.x),
                                       tanh_ap(C[t][1] + qv.y));
        *(__half2*)&sH16[lr*112 + col] = hv;
    }
}

__global__ __launch_bounds__(NT) void pos_main(
    const int*   __restrict__ input,
    const float* __restrict__ emb,
    const float* __restrict__ conv_b,
    const float* __restrict__ fc1_w,
    const float* __restrict__ fc1_b,
    const float* __restrict__ out_b,
    float*       __restrict__ out,
    int nb)
{
    extern __shared__ char smb[];
    const char* sWB  = smb + OFFB_WB;
    const char* sWB2 = smb + OFFB_WB2;
    float*  sFb  = (float*)(smb + OFFB_FB);
    float*  sOb  = (float*)(smb + OFFB_OB);
    float*  sCb  = (float*)(smb + OFFB_CB);

    const int tid = threadIdx.x;

    // -- fill shared tables --
    {
        const int4* ps = (const int4*)g_P4b;           // 1600 int4
        int4* pd = (int4*)(smb + OFFB_P4);
        for (int i = tid; i < 1600; i += NT) pd[i] = ps[i];
        const int4* bs = (const int4*)g_WpB;           // 2080 int4
        int4* bd = (int4*)(smb + OFFB_WB);
        for (int i = tid; i < 2080; i += NT) bd[i] = bs[i];
        const int4* b2 = (const int4*)g_OwB;           // 560 int4
        int4* bd2 = (int4*)(smb + OFFB_WB2);
        for (int i = tid; i < 560; i += NT) bd2[i] = b2[i];
        if (tid < HIDc)  sFb[tid] = fc1_b[tid];
        if (tid < TAGSc) sOb[tid] = out_b[tid];
        if (tid < OCc)   sCb[tid] = conv_b[tid];
    }
    __syncthreads();

    const int warp = tid >> 5, lane = tid & 31;
    const int pair = warp >> 1, sub = warp & 1;
    char* ws = smb + OFFB_WS + pair*PSB;
    unsigned short* sIds = (unsigned short*)ws;         // [8*105] u16
    __half* pool16 = (__half*)(ws + POOL_OFF);          // [8][160] fp16
    float*  Qs     = (float*)(ws + QS_OFF);             // [8][104] f32
    __half* sH16   = (__half*)(ws + SH_OFF);            // [8][112] fp16

    const int myb = sub*4;   // this warp owns items myb..myb+3 of the pair group

    // one-time pad zeroing (each warp zeroes its 4 rows)
    for (int i = lane; i < 40; i += 32)
        pool16[(myb + i/10)*160 + 150 + (i%10)] = __half(0.f);
    if (lane < 16)
        *(uint32_t*)&sH16[(myb + (lane >> 2))*112 + 104 + (lane & 3)*2] = 0u;

    // conv lane mapping: half-warp = item of pair, lane&15 = oc pair
    const int lp   = lane & 15;
    const int hw   = lane >> 4;
    const bool cact = (lp < 15);
    const char* Pk01 = smb + OFFB_P4 + lp*8;               // (k0,k1) pairs
    const char* Pk2  = smb + OFFB_P4 + 128 + hw*64 + lp*4; // k2, per-halfwarp copy
    __half2 cbh = __floats2half2_rn(0.f, 0.f);
    if (cact) cbh = __floats2half2_rn(sCb[2*lp], sCb[2*lp+1]);

    const int j0 = lane*4;
    const int lr = lane >> 2, lq = lane & 3;
    const int ngroups = (nb + ITP - 1) / ITP;

    for (int group = blockIdx.x*NPAIR + pair; group < ngroups; group += gridDim.x*NPAIR) {
        const int base = group*ITP;
        const int nit = (nb - base < ITP) ? (nb - base) : ITP;
        int mynit = nit - myb; mynit = mynit < 0 ? 0 : (mynit > 4 ? 4 : mynit);

        // ids for my 4 items; char slots pre-scaled to row byte offsets (c*256)
        for (int i = lane; i < mynit*ROWI; i += 32) {
            int v = input[(base + myb)*ROWI + i];
            sIds[myb*ROWI + i] = (unsigned short)(((i % 21) == 0) ? v : (v << 8));
        }
        if (mynit < 4)
            for (int i = mynit*ROWI + lane; i < 4*ROWI; i += 32) sIds[myb*ROWI + i] = 0;
        __syncwarp();

        // -- conv + maxpool: 2 of my items/pass, half2 over oc pairs -> pool fp16 --
        if (cact) {
            #pragma unroll
            for (int ip = 0; ip < 2; ip++) {
                const int it = myb + ip*2 + hw;
                #pragma unroll 1
                for (int w = 0; w < WW; w++) {
                    const unsigned short* cc = &sIds[it*ROWI + w*21 + 1];
                    __half2 m  = __floats2half2_rn(-60000.f, -60000.f);
                    __half2 s1 = __floats2half2_rn(0.f, 0.f);
                    __half2 s0 = s1;
                    #pragma unroll
                    for (int p = 0; p < LL; p++) {
                        const int c = cc[p];
                        uint2    r01 = *(const uint2*)(Pk01 + c);
                        uint32_t r2v = *(const uint32_t*)(Pk2 + c);
                        __half2 v0 = *(const __half2*)&r01.x;
                        __half2 v1 = *(const __half2*)&r01.y;
                        __half2 v2 = *(const __half2*)&r2v;
                        if (p >= 2) m = __hmax2(m, __hadd2(s1, v2));
                        s1 = __hadd2(s0, v1);
                        s0 = v0;
                    }
                    *(__half2*)&pool16[it*160 + w*OCc + 2*lp] = __hadd2(m, cbh);
                }
            }
        }

        // -- Q phase for my 4 items: Qs[it][j] = sum_w Qtable + fc1_b (fp32) --
        if (lane < 26) {
            for (int itl = 0; itl < 4; itl++) {
                const int it = myb + itl;
                float4 acc = {0.f, 0.f, 0.f, 0.f};
                if (lane < 25) {
                    if (itl < mynit) {
                        #pragma unroll
                        for (int w = 0; w < WW; w++) {
                            int id = sIds[it*ROWI + w*21];
                            if (id < QN) {
                                const float4 q = *(const float4*)&g_Q[(w*QN + id)*HIDc + j0];
                                acc.x += q.x; acc.y += q.y; acc.z += q.z; acc.w += q.w;
                            } else {   // exact fallback (never taken for this data)
                                const float* e = emb + (long)id*WEc;
                                #pragma unroll 1
                                for (int d = 0; d < WEc; d++) {
                                    float ev = e[d];
                                    acc.x += ev * fc1_w[(j0+0)*FCIN + w*WSTR + d];
                                    acc.y += ev * fc1_w[(j0+1)*FCIN + w*WSTR + d];
                                    acc.z += ev * fc1_w[(j0+2)*FCIN + w*WSTR + d];
                                    acc.w += ev * fc1_w[(j0+3)*FCIN + w*WSTR + d];
                                }
                            }
                        }
                    }
                    acc.x += sFb[j0+0]; acc.y += sFb[j0+1];
                    acc.z += sFb[j0+2]; acc.w += sFb[j0+3];
                }
                *(float4*)&Qs[it*104 + j0] = acc;
            }
        }

        pair_bar(pair);   // all 8 items' pool16 + Qs ready

        // -- fc1 on tensor cores, N-split across the warp pair --
        if (sub == 0) mma_fc1<0, 7>(pool16, sWB, Qs, sH16, lane);
        else          mma_fc1<7, 6>(pool16, sWB, Qs, sH16, lane);

        pair_bar(pair);   // sH16 complete

        // -- output layer on tensor cores, N-split: sub0 tiles 0-2, sub1 tiles 3-4 --
        {
            const int t0 = sub ? 3 : 0;
            const int tn = sub ? 2 : 3;
            float C[3][4];
            #pragma unroll
            for (int t = 0; t < 3; t++) { C[t][0]=0.f; C[t][1]=0.f; C[t][2]=0.f; C[t][3]=0.f; }
            #pragma unroll
            for (int kt = 0; kt < KT2; kt++) {
                uint32_t a0 = *(const uint32_t*)&sH16[lr*112 + kt*16 + lq*2];
                uint32_t a2 = *(const uint32_t*)&sH16[lr*112 + kt*16 + lq*2 + 8];
                #pragma unroll
                for (int t = 0; t < 3; t++) {
                    if (t < tn) {
                        uint2 b = *(const uint2*)(sWB2 + ((kt*NT2 + t0 + t)*32 + lane)*8);
                        mma16816(C[t][0], C[t][1], C[t][2], C[t][3], a0, a0, a2, a2, b.x, b.y);
                    }
                }
            }
            if (lr < nit) {
                float* orow = out + (long)(base + lr)*TAGSc;
                #pragma unroll
                for (int t = 0; t < 3; t++) {
                    if (t < tn) {
                        int c = (t0 + t)*8 + lq*2;
                        if (c < TAGSc)     orow[c]     = C[t][0] + sOb[c];
                        if (c + 1 < TAGSc) orow[c + 1] = C[t][1] + sOb[c + 1];
                    }
                }
            }
        }
        // next iteration's barA orders these reads before sH16/pool overwrite
    }
}

extern "C" void kernel_launch(void* const* d_in, const int* in_sizes, int n_in,
                              void* d_out, int out_size) {
    const int*   input = (const int*)  d_in[0];
    const float* emb   = (const float*)d_in[1];
    const float* cemb  = (const float*)d_in[2];
    const float* convw = (const float*)d_in[3];
    const float* convb = (const float*)d_in[4];
    const float* fc1w  = (const float*)d_in[5];
    const float* fc1b  = (const float*)d_in[6];
    const float* outw  = (const float*)d_in[7];
    const float* outb  = (const float*)d_in[8];
    float* out = (float*)d_out;

    int nb = in_sizes[0] / ROWI;

    cudaFuncSetAttribute(pos_main, cudaFuncAttributeMaxDynamicSharedMemorySize, SM_BYTES);

    int tail_blocks = (NB_ + NB2_ + NP + 255)/256;     // 33
    prep_all<<<QCB + tail_blocks, 256>>>(convw, cemb, emb, fc1w, outw);

    pos_main<<<148, NT, SM_BYTES>>>(input, emb, convb, fc1w, fc1b, outb, out, nb);
}